// round 1
// baseline (speedup 1.0000x reference)
#include <cuda_runtime.h>
#include <cuda_bf16.h>
#include <math.h>

// Problem constants
#define L_    32768
#define C_    512
#define H_    8
#define D_    64
#define E_    1048576
#define HID_  1024

// ---------------------------------------------------------------------------
// Scratch (device globals; no allocation allowed)
// ---------------------------------------------------------------------------
__device__ float g_z[(size_t)L_ * C_];     // LN output (reused for both LNs)
__device__ float g_q[(size_t)L_ * C_];
__device__ float g_k[(size_t)L_ * C_];
__device__ float g_v[(size_t)L_ * C_];
__device__ float g_att[(size_t)L_ * C_];   // attention output pre-Wo
__device__ float g_h[(size_t)L_ * HID_];   // MLP hidden
__device__ int   g_seg[L_ + 1];            // segment starts

// ---------------------------------------------------------------------------
// LayerNorm: one block per row, 256 threads, 2 floats/thread
// ---------------------------------------------------------------------------
__global__ __launch_bounds__(256) void ln_kernel(
    const float* __restrict__ x, const float* __restrict__ g,
    const float* __restrict__ b, float* __restrict__ z)
{
    int l = blockIdx.x, tid = threadIdx.x;
    const float2* xr = (const float2*)(x + (size_t)l * C_);
    float2 v = xr[tid];
    float s  = v.x + v.y;
    float ss = v.x * v.x + v.y * v.y;
    #pragma unroll
    for (int m = 16; m >= 1; m >>= 1) {
        s  += __shfl_xor_sync(0xffffffffu, s,  m);
        ss += __shfl_xor_sync(0xffffffffu, ss, m);
    }
    __shared__ float sb[8], ssb[8], stat[2];
    int wid = tid >> 5, lane = tid & 31;
    if (lane == 0) { sb[wid] = s; ssb[wid] = ss; }
    __syncthreads();
    if (tid == 0) {
        float S = 0.f, SS = 0.f;
        #pragma unroll
        for (int w = 0; w < 8; w++) { S += sb[w]; SS += ssb[w]; }
        float mu  = S * (1.f / 512.f);
        float var = SS * (1.f / 512.f) - mu * mu;
        stat[0] = mu;
        stat[1] = rsqrtf(var + 1e-5f);
    }
    __syncthreads();
    float mu = stat[0], rstd = stat[1];
    float2 gg = ((const float2*)g)[tid];
    float2 bb = ((const float2*)b)[tid];
    float2 o;
    o.x = (v.x - mu) * rstd * gg.x + bb.x;
    o.y = (v.y - mu) * rstd * gg.y + bb.y;
    ((float2*)(z + (size_t)l * C_))[tid] = o;
}

// ---------------------------------------------------------------------------
// Segment boundaries from sorted row_index
// ---------------------------------------------------------------------------
__global__ void seg_kernel(const int* __restrict__ row, int* __restrict__ seg)
{
    int e = blockIdx.x * blockDim.x + threadIdx.x;
    if (e >= E_) return;
    int r  = row[e];
    int rp = (e == 0) ? -1 : row[e - 1];
    for (int l = rp + 1; l <= r; l++) seg[l] = e;
    if (e == E_ - 1) {
        for (int l = r + 1; l <= L_; l++) seg[l] = E_;
    }
}

// ---------------------------------------------------------------------------
// Sparse attention: one block (256 thr = 8 warps) per destination row.
// Online softmax over edge chunks of SMAX. Lane layout: lane owns float4
// index r*32+lane for r=0..3; head of chunk r = 2r + (lane>=16).
// ---------------------------------------------------------------------------
#define SMAX 256

__global__ __launch_bounds__(256) void attn_kernel(
    const float* __restrict__ Q, const float* __restrict__ K,
    const float* __restrict__ V, const float* __restrict__ bias,
    const int* __restrict__ col, const int* __restrict__ seg,
    float* __restrict__ out)
{
    __shared__ float sq[C_];
    __shared__ float sc[SMAX * H_];
    __shared__ float red[8 * C_];
    __shared__ float rm[H_], rs[H_], rf[H_];

    int l = blockIdx.x;
    int tid = threadIdx.x;
    int wid = tid >> 5, lane = tid & 31;
    int hb = lane >> 4;   // 0 for lanes 0-15, 1 for lanes 16-31

    {   // load q row, fold in 1/sqrt(D) = 1/8
        const float2* qr = (const float2*)(Q + (size_t)l * C_);
        float2 t = qr[tid];
        t.x *= 0.125f; t.y *= 0.125f;
        ((float2*)sq)[tid] = t;
    }
    if (tid < H_) { rm[tid] = -1e30f; rs[tid] = 0.f; }
    __syncthreads();

    int e0 = seg[l], e1 = seg[l + 1];

    float acc[16];
    #pragma unroll
    for (int i = 0; i < 16; i++) acc[i] = 0.f;

    const float4* sq4 = (const float4*)sq;

    for (int c0 = e0; c0 < e1; c0 += SMAX) {
        int cn = min(SMAX, e1 - c0);

        // ---- scores: each warp handles edges i = wid, wid+8, ...
        for (int i = wid; i < cn; i += 8) {
            int e  = c0 + i;
            int cx = col[e];
            const float4* kp = (const float4*)(K + (size_t)cx * C_);
            float pd[4];
            #pragma unroll
            for (int r = 0; r < 4; r++) {
                float4 kk = kp[r * 32 + lane];
                float4 qq = sq4[r * 32 + lane];
                pd[r] = kk.x * qq.x + kk.y * qq.y + kk.z * qq.z + kk.w * qq.w;
            }
            #pragma unroll
            for (int m = 1; m < 16; m <<= 1) {
                #pragma unroll
                for (int r = 0; r < 4; r++)
                    pd[r] += __shfl_xor_sync(0xffffffffu, pd[r], m);
            }
            if ((lane & 15) == 0) {
                #pragma unroll
                for (int r = 0; r < 4; r++) {
                    int h = 2 * r + hb;
                    sc[i * H_ + h] = pd[r] + bias[(size_t)e * H_ + h];
                }
            }
        }
        __syncthreads();

        // ---- per-head running max / sum: warp `wid` owns head `wid`
        {
            int h = wid;
            float mx = -1e30f;
            for (int i = lane; i < cn; i += 32) mx = fmaxf(mx, sc[i * H_ + h]);
            #pragma unroll
            for (int m = 16; m >= 1; m >>= 1)
                mx = fmaxf(mx, __shfl_xor_sync(0xffffffffu, mx, m));
            float oldm = rm[h];
            float newm = fmaxf(oldm, mx);
            float fac  = __expf(oldm - newm);   // 0 on first chunk
            float ps = 0.f;
            for (int i = lane; i < cn; i += 32) {
                float p = __expf(sc[i * H_ + h] - newm);
                sc[i * H_ + h] = p;
                ps += p;
            }
            #pragma unroll
            for (int m = 16; m >= 1; m >>= 1)
                ps += __shfl_xor_sync(0xffffffffu, ps, m);
            if (lane == 0) {
                rs[h] = rs[h] * fac + ps;
                rm[h] = newm;
                rf[h] = fac;
            }
        }
        __syncthreads();

        // ---- rescale accumulators (per-lane head per r-chunk)
        #pragma unroll
        for (int r = 0; r < 4; r++) {
            float f = rf[2 * r + hb];
            acc[4 * r + 0] *= f; acc[4 * r + 1] *= f;
            acc[4 * r + 2] *= f; acc[4 * r + 3] *= f;
        }

        // ---- weighted V accumulation
        for (int i = wid; i < cn; i += 8) {
            int e  = c0 + i;
            int cx = col[e];
            const float4* vp = (const float4*)(V + (size_t)cx * C_);
            #pragma unroll
            for (int r = 0; r < 4; r++) {
                float p = sc[i * H_ + 2 * r + hb];
                float4 vv = vp[r * 32 + lane];
                acc[4 * r + 0] += p * vv.x;
                acc[4 * r + 1] += p * vv.y;
                acc[4 * r + 2] += p * vv.z;
                acc[4 * r + 3] += p * vv.w;
            }
        }
        __syncthreads();   // protect sc / rm / rs for next chunk
    }

    // ---- cross-warp reduce + normalize
    #pragma unroll
    for (int r = 0; r < 4; r++) {
        float4 t = make_float4(acc[4 * r + 0], acc[4 * r + 1],
                               acc[4 * r + 2], acc[4 * r + 3]);
        ((float4*)red)[wid * 128 + r * 32 + lane] = t;
    }
    __syncthreads();
    #pragma unroll
    for (int it = 0; it < 2; it++) {
        int d = tid + it * 256;
        float s = 0.f;
        #pragma unroll
        for (int w = 0; w < 8; w++) s += red[w * C_ + d];
        float den = rs[d >> 6];
        out[(size_t)l * C_ + d] = (den > 0.f) ? s / den : 0.f;
    }
}

// ---------------------------------------------------------------------------
// SGEMM: C = A(MxK) @ B(KxN) + bias, optional epilogue.
// EPI: 0 = none, 1 = SiLU, 2 = + res (residual add).
// 128x128x8 tile, 8x8 microtile, 256 threads, double-buffered smem.
// M % 128 == 0, N % 128 == 0, K % 8 == 0 (all shapes here comply).
// ---------------------------------------------------------------------------
template <int EPI>
__global__ __launch_bounds__(256, 2) void sgemm_kernel(
    const float* __restrict__ A, const float* __restrict__ B,
    const float* __restrict__ bias, const float* __restrict__ res,
    float* __restrict__ C, int M, int N, int K)
{
    const int BM = 128, BN = 128, BK = 8, TM = 8, TN = 8;
    __shared__ float As[2][BK][BM];
    __shared__ float Bs[2][BK][BN];

    int tid = threadIdx.x;
    int bx = blockIdx.x, by = blockIdx.y;
    int tx = tid & 15, ty = tid >> 4;

    int a_row = tid >> 1;
    int a_kv  = (tid & 1) * 4;
    int b_kr  = tid >> 5;
    int b_nc  = (tid & 31) * 4;

    const float* Ap = A + (size_t)(by * BM + a_row) * K + a_kv;
    const float* Bp = B + (size_t)b_kr * N + (size_t)bx * BN + b_nc;

    float acc[TM][TN];
    #pragma unroll
    for (int i = 0; i < TM; i++)
        #pragma unroll
        for (int j = 0; j < TN; j++) acc[i][j] = 0.f;

    float4 ra = *(const float4*)Ap;
    float4 rb = *(const float4*)Bp;
    As[0][a_kv + 0][a_row] = ra.x;
    As[0][a_kv + 1][a_row] = ra.y;
    As[0][a_kv + 2][a_row] = ra.z;
    As[0][a_kv + 3][a_row] = ra.w;
    *(float4*)&Bs[0][b_kr][b_nc] = rb;
    __syncthreads();

    int KT = K / BK;
    int buf = 0;
    for (int kt = 0; kt < KT; kt++) {
        if (kt + 1 < KT) {
            ra = *(const float4*)(Ap + (kt + 1) * BK);
            rb = *(const float4*)(Bp + (size_t)(kt + 1) * BK * N);
        }
        #pragma unroll
        for (int kk = 0; kk < BK; kk++) {
            float a[TM], b[TN];
            *(float4*)&a[0] = *(const float4*)&As[buf][kk][ty * TM];
            *(float4*)&a[4] = *(const float4*)&As[buf][kk][ty * TM + 4];
            *(float4*)&b[0] = *(const float4*)&Bs[buf][kk][tx * TN];
            *(float4*)&b[4] = *(const float4*)&Bs[buf][kk][tx * TN + 4];
            #pragma unroll
            for (int i = 0; i < TM; i++)
                #pragma unroll
                for (int j = 0; j < TN; j++)
                    acc[i][j] += a[i] * b[j];
        }
        if (kt + 1 < KT) {
            int nb = buf ^ 1;
            As[nb][a_kv + 0][a_row] = ra.x;
            As[nb][a_kv + 1][a_row] = ra.y;
            As[nb][a_kv + 2][a_row] = ra.z;
            As[nb][a_kv + 3][a_row] = ra.w;
            *(float4*)&Bs[nb][b_kr][b_nc] = rb;
            __syncthreads();
            buf = nb;
        }
    }

    int crow = by * BM + ty * TM;
    int ccol = bx * BN + tx * TN;
    #pragma unroll
    for (int i = 0; i < TM; i++) {
        #pragma unroll
        for (int jv = 0; jv < 2; jv++) {
            float4 o;
            float* oc = &o.x;
            #pragma unroll
            for (int j = 0; j < 4; j++) {
                float v = acc[i][jv * 4 + j] + bias[ccol + jv * 4 + j];
                if (EPI == 1) v = v / (1.f + __expf(-v));
                if (EPI == 2) v += res[(size_t)(crow + i) * N + ccol + jv * 4 + j];
                oc[j] = v;
            }
            *(float4*)&C[(size_t)(crow + i) * N + ccol + jv * 4] = o;
        }
    }
}

// ---------------------------------------------------------------------------
// Launch
// ---------------------------------------------------------------------------
extern "C" void kernel_launch(void* const* d_in, const int* in_sizes, int n_in,
                              void* d_out, int out_size)
{
    const float *x, *att_bias, *Wq, *bq, *Wk, *bk, *Wv, *bv, *Wo, *bo;
    const float *ln1g, *ln1b, *ln2g, *ln2b, *W1, *b1, *W2, *b2;
    const int *row, *col;

    if (in_sizes[1] == E_ * H_) {
        // reference-signature order:
        // x, att_bias, Wq,bq,Wk,bk,Wv,bv,Wo,bo, ln1_g,ln1_b,ln2_g,ln2_b,
        // W1,b1,W2,b2, row_index, col_index
        x        = (const float*)d_in[0];
        att_bias = (const float*)d_in[1];
        Wq = (const float*)d_in[2];  bq = (const float*)d_in[3];
        Wk = (const float*)d_in[4];  bk = (const float*)d_in[5];
        Wv = (const float*)d_in[6];  bv = (const float*)d_in[7];
        Wo = (const float*)d_in[8];  bo = (const float*)d_in[9];
        ln1g = (const float*)d_in[10]; ln1b = (const float*)d_in[11];
        ln2g = (const float*)d_in[12]; ln2b = (const float*)d_in[13];
        W1 = (const float*)d_in[14]; b1 = (const float*)d_in[15];
        W2 = (const float*)d_in[16]; b2 = (const float*)d_in[17];
        row = (const int*)d_in[18];  col = (const int*)d_in[19];
    } else {
        // setup_inputs dict order:
        // x, row_index, col_index, att_bias, Wq,bq,Wk,bk,Wv,bv,Wo,bo,
        // ln1_g,ln1_b,ln2_g,ln2_b, W1,b1,W2,b2
        x   = (const float*)d_in[0];
        row = (const int*)d_in[1];
        col = (const int*)d_in[2];
        att_bias = (const float*)d_in[3];
        Wq = (const float*)d_in[4];  bq = (const float*)d_in[5];
        Wk = (const float*)d_in[6];  bk = (const float*)d_in[7];
        Wv = (const float*)d_in[8];  bv = (const float*)d_in[9];
        Wo = (const float*)d_in[10]; bo = (const float*)d_in[11];
        ln1g = (const float*)d_in[12]; ln1b = (const float*)d_in[13];
        ln2g = (const float*)d_in[14]; ln2b = (const float*)d_in[15];
        W1 = (const float*)d_in[16]; b1 = (const float*)d_in[17];
        W2 = (const float*)d_in[18]; b2 = (const float*)d_in[19];
    }

    float *pz, *pq, *pk, *pv, *pa, *ph;
    int* pseg;
    cudaGetSymbolAddress((void**)&pz, g_z);
    cudaGetSymbolAddress((void**)&pq, g_q);
    cudaGetSymbolAddress((void**)&pk, g_k);
    cudaGetSymbolAddress((void**)&pv, g_v);
    cudaGetSymbolAddress((void**)&pa, g_att);
    cudaGetSymbolAddress((void**)&ph, g_h);
    cudaGetSymbolAddress((void**)&pseg, g_seg);

    float* out = (float*)d_out;

    // 1. z = LN1(x)
    ln_kernel<<<L_, 256>>>(x, ln1g, ln1b, pz);
    // 2. segment boundaries
    seg_kernel<<<E_ / 256, 256>>>(row, pseg);
    // 3. q, k, v projections
    dim3 gC(C_ / 128, L_ / 128);
    sgemm_kernel<0><<<gC, 256>>>(pz, Wq, bq, nullptr, pq, L_, C_, C_);
    sgemm_kernel<0><<<gC, 256>>>(pz, Wk, bk, nullptr, pk, L_, C_, C_);
    sgemm_kernel<0><<<gC, 256>>>(pz, Wv, bv, nullptr, pv, L_, C_, C_);
    // 4. sparse attention
    attn_kernel<<<L_, 256>>>(pq, pk, pv, att_bias, col, pseg, pa);
    // 5. out = x + att @ Wo + bo
    sgemm_kernel<2><<<gC, 256>>>(pa, Wo, bo, x, out, L_, C_, C_);
    // 6. z = LN2(out)
    ln_kernel<<<L_, 256>>>(out, ln2g, ln2b, pz);
    // 7. h = silu(z @ W1 + b1)
    dim3 gH(HID_ / 128, L_ / 128);
    sgemm_kernel<1><<<gH, 256>>>(pz, W1, b1, nullptr, ph, L_, HID_, C_);
    // 8. out = out + h @ W2 + b2
    sgemm_kernel<2><<<gC, 256>>>(ph, W2, b2, out, out, L_, C_, HID_);
}

// round 3
// speedup vs baseline: 1.8079x; 1.8079x over previous
#include <cuda_runtime.h>
#include <cuda_bf16.h>
#include <math.h>
#include <cstdint>
#include <stdint.h>

// Problem constants
#define L_    32768
#define C_    512
#define H_    8
#define D_    64
#define E_    1048576
#define HID_  1024

// ---------------------------------------------------------------------------
// Scratch (device globals; no allocation allowed)
// ---------------------------------------------------------------------------
__device__ float g_z[(size_t)L_ * C_];     // LN output (reused for both LNs)
__device__ float g_q[(size_t)L_ * C_];
__device__ float g_k[(size_t)L_ * C_];
__device__ float g_v[(size_t)L_ * C_];
__device__ float g_att[(size_t)L_ * C_];   // attention output pre-Wo
__device__ float g_h[(size_t)L_ * HID_];   // MLP hidden
__device__ int   g_seg[L_ + 1];            // segment starts

// ---------------------------------------------------------------------------
// LayerNorm: one block per row, 256 threads, 2 floats/thread
// ---------------------------------------------------------------------------
__global__ __launch_bounds__(256) void ln_kernel(
    const float* __restrict__ x, const float* __restrict__ g,
    const float* __restrict__ b, float* __restrict__ z)
{
    int l = blockIdx.x, tid = threadIdx.x;
    const float2* xr = (const float2*)(x + (size_t)l * C_);
    float2 v = xr[tid];
    float s  = v.x + v.y;
    float ss = v.x * v.x + v.y * v.y;
    #pragma unroll
    for (int m = 16; m >= 1; m >>= 1) {
        s  += __shfl_xor_sync(0xffffffffu, s,  m);
        ss += __shfl_xor_sync(0xffffffffu, ss, m);
    }
    __shared__ float sb[8], ssb[8], stat[2];
    int wid = tid >> 5, lane = tid & 31;
    if (lane == 0) { sb[wid] = s; ssb[wid] = ss; }
    __syncthreads();
    if (tid == 0) {
        float S = 0.f, SS = 0.f;
        #pragma unroll
        for (int w = 0; w < 8; w++) { S += sb[w]; SS += ssb[w]; }
        float mu  = S * (1.f / 512.f);
        float var = SS * (1.f / 512.f) - mu * mu;
        stat[0] = mu;
        stat[1] = rsqrtf(var + 1e-5f);
    }
    __syncthreads();
    float mu = stat[0], rstd = stat[1];
    float2 gg = ((const float2*)g)[tid];
    float2 bb = ((const float2*)b)[tid];
    float2 o;
    o.x = (v.x - mu) * rstd * gg.x + bb.x;
    o.y = (v.y - mu) * rstd * gg.y + bb.y;
    ((float2*)(z + (size_t)l * C_))[tid] = o;
}

// ---------------------------------------------------------------------------
// Segment boundaries from sorted row_index
// ---------------------------------------------------------------------------
__global__ void seg_kernel(const int* __restrict__ row, int* __restrict__ seg)
{
    int e = blockIdx.x * blockDim.x + threadIdx.x;
    if (e >= E_) return;
    int r  = row[e];
    int rp = (e == 0) ? -1 : row[e - 1];
    for (int l = rp + 1; l <= r; l++) seg[l] = e;
    if (e == E_ - 1) {
        for (int l = r + 1; l <= L_; l++) seg[l] = E_;
    }
}

// ---------------------------------------------------------------------------
// Sparse attention: one block (256 thr = 8 warps) per destination row.
// ---------------------------------------------------------------------------
#define SMAX 256

__global__ __launch_bounds__(256) void attn_kernel(
    const float* __restrict__ Q, const float* __restrict__ K,
    const float* __restrict__ V, const float* __restrict__ bias,
    const int* __restrict__ col, const int* __restrict__ seg,
    float* __restrict__ out)
{
    __shared__ float sq[C_];
    __shared__ float sc[SMAX * H_];
    __shared__ float red[8 * C_];
    __shared__ float rm[H_], rs[H_], rf[H_];

    int l = blockIdx.x;
    int tid = threadIdx.x;
    int wid = tid >> 5, lane = tid & 31;
    int hb = lane >> 4;

    {
        const float2* qr = (const float2*)(Q + (size_t)l * C_);
        float2 t = qr[tid];
        t.x *= 0.125f; t.y *= 0.125f;
        ((float2*)sq)[tid] = t;
    }
    if (tid < H_) { rm[tid] = -1e30f; rs[tid] = 0.f; }
    __syncthreads();

    int e0 = seg[l], e1 = seg[l + 1];

    float acc[16];
    #pragma unroll
    for (int i = 0; i < 16; i++) acc[i] = 0.f;

    const float4* sq4 = (const float4*)sq;

    for (int c0 = e0; c0 < e1; c0 += SMAX) {
        int cn = min(SMAX, e1 - c0);

        for (int i = wid; i < cn; i += 8) {
            int e  = c0 + i;
            int cx = col[e];
            const float4* kp = (const float4*)(K + (size_t)cx * C_);
            float pd[4];
            #pragma unroll
            for (int r = 0; r < 4; r++) {
                float4 kk = kp[r * 32 + lane];
                float4 qq = sq4[r * 32 + lane];
                pd[r] = kk.x * qq.x + kk.y * qq.y + kk.z * qq.z + kk.w * qq.w;
            }
            #pragma unroll
            for (int m = 1; m < 16; m <<= 1) {
                #pragma unroll
                for (int r = 0; r < 4; r++)
                    pd[r] += __shfl_xor_sync(0xffffffffu, pd[r], m);
            }
            if ((lane & 15) == 0) {
                #pragma unroll
                for (int r = 0; r < 4; r++) {
                    int h = 2 * r + hb;
                    sc[i * H_ + h] = pd[r] + bias[(size_t)e * H_ + h];
                }
            }
        }
        __syncthreads();

        {
            int h = wid;
            float mx = -1e30f;
            for (int i = lane; i < cn; i += 32) mx = fmaxf(mx, sc[i * H_ + h]);
            #pragma unroll
            for (int m = 16; m >= 1; m >>= 1)
                mx = fmaxf(mx, __shfl_xor_sync(0xffffffffu, mx, m));
            float oldm = rm[h];
            float newm = fmaxf(oldm, mx);
            float fac  = __expf(oldm - newm);
            float ps = 0.f;
            for (int i = lane; i < cn; i += 32) {
                float p = __expf(sc[i * H_ + h] - newm);
                sc[i * H_ + h] = p;
                ps += p;
            }
            #pragma unroll
            for (int m = 16; m >= 1; m >>= 1)
                ps += __shfl_xor_sync(0xffffffffu, ps, m);
            if (lane == 0) {
                rs[h] = rs[h] * fac + ps;
                rm[h] = newm;
                rf[h] = fac;
            }
        }
        __syncthreads();

        #pragma unroll
        for (int r = 0; r < 4; r++) {
            float f = rf[2 * r + hb];
            acc[4 * r + 0] *= f; acc[4 * r + 1] *= f;
            acc[4 * r + 2] *= f; acc[4 * r + 3] *= f;
        }

        for (int i = wid; i < cn; i += 8) {
            int e  = c0 + i;
            int cx = col[e];
            const float4* vp = (const float4*)(V + (size_t)cx * C_);
            #pragma unroll
            for (int r = 0; r < 4; r++) {
                float p = sc[i * H_ + 2 * r + hb];
                float4 vv = vp[r * 32 + lane];
                acc[4 * r + 0] += p * vv.x;
                acc[4 * r + 1] += p * vv.y;
                acc[4 * r + 2] += p * vv.z;
                acc[4 * r + 3] += p * vv.w;
            }
        }
        __syncthreads();
    }

    #pragma unroll
    for (int r = 0; r < 4; r++) {
        float4 t = make_float4(acc[4 * r + 0], acc[4 * r + 1],
                               acc[4 * r + 2], acc[4 * r + 3]);
        ((float4*)red)[wid * 128 + r * 32 + lane] = t;
    }
    __syncthreads();
    #pragma unroll
    for (int it = 0; it < 2; it++) {
        int d = tid + it * 256;
        float s = 0.f;
        #pragma unroll
        for (int w = 0; w < 8; w++) s += red[w * C_ + d];
        float den = rs[d >> 6];
        out[(size_t)l * C_ + d] = (den > 0.f) ? s / den : 0.f;
    }
}

// ---------------------------------------------------------------------------
// TF32 tensor-core GEMM: C = A(MxK) @ B(KxN) + bias, optional epilogue.
// EPI: 0 = none, 1 = SiLU, 2 = + res.
// 128x128x16 tile, 256 threads = 8 warps (2x4), warptile 64x32 via
// mma.sync.m16n8k8 tf32 (RNA-rounded inputs, fp32 accumulate).
// Requires M%128==0, N%128==0, K%16==0.
// ---------------------------------------------------------------------------
__device__ __forceinline__ float f2tf32(float x) {
    unsigned int u;
    asm("cvt.rna.tf32.f32 %0, %1;" : "=r"(u) : "f"(x));
    return __uint_as_float(u);
}

template <int EPI>
__global__ __launch_bounds__(256, 2) void tgemm_kernel(
    const float* __restrict__ A, const float* __restrict__ B,
    const float* __restrict__ bias, const float* __restrict__ res,
    float* __restrict__ C, int M, int N, int K)
{
    const int BM = 128, BN = 128, BK = 16;
    __shared__ float As[2][BK][BM + 4];
    __shared__ float Bs[2][BK][BN + 4];

    int tid = threadIdx.x;
    int bx = blockIdx.x, by = blockIdx.y;
    int lane = tid & 31, wid = tid >> 5;
    int wm = (wid & 1) * 64, wn = (wid >> 1) * 32;
    int g = lane >> 2, t = lane & 3;

    int a_row = tid >> 1;
    int a_k   = (tid & 1) * 4;
    int b_k   = tid >> 5;
    int b_n   = (tid & 31) * 4;

    const float* Ap = A + (size_t)(by * BM + a_row) * K + a_k;
    const float* Bp = B + (size_t)b_k * N + (size_t)bx * BN + b_n;

    float acc[4][4][4];
    #pragma unroll
    for (int mi = 0; mi < 4; mi++)
        #pragma unroll
        for (int ni = 0; ni < 4; ni++)
            #pragma unroll
            for (int r = 0; r < 4; r++) acc[mi][ni][r] = 0.f;

    // prologue: tile 0
    {
        float4 ra0 = *(const float4*)(Ap);
        float4 ra1 = *(const float4*)(Ap + 8);
        float4 rb0 = *(const float4*)(Bp);
        float4 rb1 = *(const float4*)(Bp + (size_t)8 * N);
        As[0][a_k + 0][a_row] = f2tf32(ra0.x);
        As[0][a_k + 1][a_row] = f2tf32(ra0.y);
        As[0][a_k + 2][a_row] = f2tf32(ra0.z);
        As[0][a_k + 3][a_row] = f2tf32(ra0.w);
        As[0][a_k + 8][a_row] = f2tf32(ra1.x);
        As[0][a_k + 9][a_row] = f2tf32(ra1.y);
        As[0][a_k +10][a_row] = f2tf32(ra1.z);
        As[0][a_k +11][a_row] = f2tf32(ra1.w);
        float4 c0 = make_float4(f2tf32(rb0.x), f2tf32(rb0.y), f2tf32(rb0.z), f2tf32(rb0.w));
        float4 c1 = make_float4(f2tf32(rb1.x), f2tf32(rb1.y), f2tf32(rb1.z), f2tf32(rb1.w));
        *(float4*)&Bs[0][b_k][b_n]     = c0;
        *(float4*)&Bs[0][b_k + 8][b_n] = c1;
    }
    __syncthreads();

    int KT = K / BK;
    int buf = 0;
    for (int kt = 0; kt < KT; kt++) {
        float4 ra0, ra1, rb0, rb1;
        if (kt + 1 < KT) {
            const float* Ap2 = Ap + (kt + 1) * BK;
            const float* Bp2 = Bp + (size_t)(kt + 1) * BK * N;
            ra0 = *(const float4*)(Ap2);
            ra1 = *(const float4*)(Ap2 + 8);
            rb0 = *(const float4*)(Bp2);
            rb1 = *(const float4*)(Bp2 + (size_t)8 * N);
        }

        #pragma unroll
        for (int ks = 0; ks < BK; ks += 8) {
            float af[4][4];
            float bf[4][2];
            #pragma unroll
            for (int mi = 0; mi < 4; mi++) {
                int r = wm + mi * 16 + g;
                af[mi][0] = As[buf][ks + t][r];
                af[mi][1] = As[buf][ks + t][r + 8];
                af[mi][2] = As[buf][ks + t + 4][r];
                af[mi][3] = As[buf][ks + t + 4][r + 8];
            }
            #pragma unroll
            for (int ni = 0; ni < 4; ni++) {
                int c = wn + ni * 8 + g;
                bf[ni][0] = Bs[buf][ks + t][c];
                bf[ni][1] = Bs[buf][ks + t + 4][c];
            }
            #pragma unroll
            for (int mi = 0; mi < 4; mi++)
                #pragma unroll
                for (int ni = 0; ni < 4; ni++) {
                    asm volatile(
                        "mma.sync.aligned.m16n8k8.row.col.f32.tf32.tf32.f32 "
                        "{%0,%1,%2,%3}, {%4,%5,%6,%7}, {%8,%9}, {%0,%1,%2,%3};\n"
                        : "+f"(acc[mi][ni][0]), "+f"(acc[mi][ni][1]),
                          "+f"(acc[mi][ni][2]), "+f"(acc[mi][ni][3])
                        : "r"(__float_as_uint(af[mi][0])), "r"(__float_as_uint(af[mi][1])),
                          "r"(__float_as_uint(af[mi][2])), "r"(__float_as_uint(af[mi][3])),
                          "r"(__float_as_uint(bf[ni][0])), "r"(__float_as_uint(bf[ni][1])));
                }
        }

        if (kt + 1 < KT) {
            int nb = buf ^ 1;
            As[nb][a_k + 0][a_row] = f2tf32(ra0.x);
            As[nb][a_k + 1][a_row] = f2tf32(ra0.y);
            As[nb][a_k + 2][a_row] = f2tf32(ra0.z);
            As[nb][a_k + 3][a_row] = f2tf32(ra0.w);
            As[nb][a_k + 8][a_row] = f2tf32(ra1.x);
            As[nb][a_k + 9][a_row] = f2tf32(ra1.y);
            As[nb][a_k +10][a_row] = f2tf32(ra1.z);
            As[nb][a_k +11][a_row] = f2tf32(ra1.w);
            float4 c0 = make_float4(f2tf32(rb0.x), f2tf32(rb0.y), f2tf32(rb0.z), f2tf32(rb0.w));
            float4 c1 = make_float4(f2tf32(rb1.x), f2tf32(rb1.y), f2tf32(rb1.z), f2tf32(rb1.w));
            *(float4*)&Bs[nb][b_k][b_n]     = c0;
            *(float4*)&Bs[nb][b_k + 8][b_n] = c1;
            __syncthreads();
            buf = nb;
        }
    }

    // epilogue: c0,c1 -> (row g, cols 2t,2t+1); c2,c3 -> (row g+8, same cols)
    #pragma unroll
    for (int mi = 0; mi < 4; mi++) {
        #pragma unroll
        for (int ni = 0; ni < 4; ni++) {
            int col = bx * BN + wn + ni * 8 + 2 * t;
            float2 bb = *(const float2*)&bias[col];
            #pragma unroll
            for (int h = 0; h < 2; h++) {
                int row = by * BM + wm + mi * 16 + g + h * 8;
                float v0 = acc[mi][ni][2 * h + 0] + bb.x;
                float v1 = acc[mi][ni][2 * h + 1] + bb.y;
                if (EPI == 1) {
                    v0 = v0 / (1.f + __expf(-v0));
                    v1 = v1 / (1.f + __expf(-v1));
                }
                if (EPI == 2) {
                    float2 rr = *(const float2*)&res[(size_t)row * N + col];
                    v0 += rr.x; v1 += rr.y;
                }
                float2 o = make_float2(v0, v1);
                *(float2*)&C[(size_t)row * N + col] = o;
            }
        }
    }
}

// ---------------------------------------------------------------------------
// Launch
// ---------------------------------------------------------------------------
extern "C" void kernel_launch(void* const* d_in, const int* in_sizes, int n_in,
                              void* d_out, int out_size)
{
    const float *x, *att_bias, *Wq, *bq, *Wk, *bk, *Wv, *bv, *Wo, *bo;
    const float *ln1g, *ln1b, *ln2g, *ln2b, *W1, *b1, *W2, *b2;
    const int *row, *col;

    if (in_sizes[1] == E_ * H_) {
        x        = (const float*)d_in[0];
        att_bias = (const float*)d_in[1];
        Wq = (const float*)d_in[2];  bq = (const float*)d_in[3];
        Wk = (const float*)d_in[4];  bk = (const float*)d_in[5];
        Wv = (const float*)d_in[6];  bv = (const float*)d_in[7];
        Wo = (const float*)d_in[8];  bo = (const float*)d_in[9];
        ln1g = (const float*)d_in[10]; ln1b = (const float*)d_in[11];
        ln2g = (const float*)d_in[12]; ln2b = (const float*)d_in[13];
        W1 = (const float*)d_in[14]; b1 = (const float*)d_in[15];
        W2 = (const float*)d_in[16]; b2 = (const float*)d_in[17];
        row = (const int*)d_in[18];  col = (const int*)d_in[19];
    } else {
        x   = (const float*)d_in[0];
        row = (const int*)d_in[1];
        col = (const int*)d_in[2];
        att_bias = (const float*)d_in[3];
        Wq = (const float*)d_in[4];  bq = (const float*)d_in[5];
        Wk = (const float*)d_in[6];  bk = (const float*)d_in[7];
        Wv = (const float*)d_in[8];  bv = (const float*)d_in[9];
        Wo = (const float*)d_in[10]; bo = (const float*)d_in[11];
        ln1g = (const float*)d_in[12]; ln1b = (const float*)d_in[13];
        ln2g = (const float*)d_in[14]; ln2b = (const float*)d_in[15];
        W1 = (const float*)d_in[16]; b1 = (const float*)d_in[17];
        W2 = (const float*)d_in[18]; b2 = (const float*)d_in[19];
    }

    float *pz, *pq, *pk, *pv, *pa, *ph;
    int* pseg;
    cudaGetSymbolAddress((void**)&pz, g_z);
    cudaGetSymbolAddress((void**)&pq, g_q);
    cudaGetSymbolAddress((void**)&pk, g_k);
    cudaGetSymbolAddress((void**)&pv, g_v);
    cudaGetSymbolAddress((void**)&pa, g_att);
    cudaGetSymbolAddress((void**)&ph, g_h);
    cudaGetSymbolAddress((void**)&pseg, g_seg);

    float* out = (float*)d_out;

    // 1. z = LN1(x)
    ln_kernel<<<L_, 256>>>(x, ln1g, ln1b, pz);
    // 2. segment boundaries
    seg_kernel<<<E_ / 256, 256>>>(row, pseg);
    // 3. q, k, v projections (tf32 tensor cores)
    dim3 gC(C_ / 128, L_ / 128);
    tgemm_kernel<0><<<gC, 256>>>(pz, Wq, bq, nullptr, pq, L_, C_, C_);
    tgemm_kernel<0><<<gC, 256>>>(pz, Wk, bk, nullptr, pk, L_, C_, C_);
    tgemm_kernel<0><<<gC, 256>>>(pz, Wv, bv, nullptr, pv, L_, C_, C_);
    // 4. sparse attention
    attn_kernel<<<L_, 256>>>(pq, pk, pv, att_bias, col, pseg, pa);
    // 5. out = x + att @ Wo + bo
    tgemm_kernel<2><<<gC, 256>>>(pa, Wo, bo, x, out, L_, C_, C_);
    // 6. z = LN2(out)
    ln_kernel<<<L_, 256>>>(out, ln2g, ln2b, pz);
    // 7. h = silu(z @ W1 + b1)
    dim3 gH(HID_ / 128, L_ / 128);
    tgemm_kernel<1><<<gH, 256>>>(pz, W1, b1, nullptr, ph, L_, HID_, C_);
    // 8. out = out + h @ W2 + b2
    tgemm_kernel<2><<<gC, 256>>>(ph, W2, b2, out, out, L_, C_, HID_);
}

// round 4
// speedup vs baseline: 2.8238x; 1.5619x over previous
#include <cuda_runtime.h>
#include <cuda_bf16.h>
#include <math.h>
#include <cstdint>
#include <stdint.h>

// Problem constants
#define L_    32768
#define C_    512
#define H_    8
#define D_    64
#define E_    1048576
#define HID_  1024

typedef __nv_bfloat16 bf16_t;

// ---------------------------------------------------------------------------
// Scratch (device globals; no allocation allowed)
// ---------------------------------------------------------------------------
__device__ bf16_t g_zb[(size_t)L_ * C_];     // LN output (bf16, reused)
__device__ float  g_q[(size_t)L_ * C_];
__device__ float  g_k[(size_t)L_ * C_];
__device__ float  g_v[(size_t)L_ * C_];
__device__ bf16_t g_attb[(size_t)L_ * C_];   // attention output (bf16)
__device__ bf16_t g_hb[(size_t)L_ * HID_];   // MLP hidden (bf16)
__device__ bf16_t g_wq[C_ * C_], g_wk[C_ * C_], g_wv[C_ * C_], g_wo[C_ * C_];
__device__ bf16_t g_w1[C_ * HID_];           // W1^T  [HID][C]
__device__ bf16_t g_w2[C_ * HID_];           // W2^T  [C][HID]
__device__ int    g_seg[L_ + 1];

// ---------------------------------------------------------------------------
// Weight transpose + cast: W (K x N, f32) -> Wt (N x K, bf16)
// ---------------------------------------------------------------------------
__global__ __launch_bounds__(256) void wcast_kernel(
    const float* __restrict__ W, bf16_t* __restrict__ Wt, int K, int N)
{
    __shared__ float t[32][33];
    int n0 = blockIdx.x * 32, k0 = blockIdx.y * 32;
    int tx = threadIdx.x, ty = threadIdx.y;
    #pragma unroll
    for (int i = 0; i < 32; i += 8)
        t[ty + i][tx] = W[(size_t)(k0 + ty + i) * N + n0 + tx];
    __syncthreads();
    #pragma unroll
    for (int i = 0; i < 32; i += 8)
        Wt[(size_t)(n0 + ty + i) * K + k0 + tx] = __float2bfloat16_rn(t[tx][ty + i]);
}

// ---------------------------------------------------------------------------
// LayerNorm: one block per row, 256 threads, 2 floats/thread; bf16 output
// ---------------------------------------------------------------------------
__global__ __launch_bounds__(256) void ln_kernel(
    const float* __restrict__ x, const float* __restrict__ g,
    const float* __restrict__ b, bf16_t* __restrict__ z)
{
    int l = blockIdx.x, tid = threadIdx.x;
    const float2* xr = (const float2*)(x + (size_t)l * C_);
    float2 v = xr[tid];
    float s  = v.x + v.y;
    float ss = v.x * v.x + v.y * v.y;
    #pragma unroll
    for (int m = 16; m >= 1; m >>= 1) {
        s  += __shfl_xor_sync(0xffffffffu, s,  m);
        ss += __shfl_xor_sync(0xffffffffu, ss, m);
    }
    __shared__ float sb[8], ssb[8], stat[2];
    int wid = tid >> 5, lane = tid & 31;
    if (lane == 0) { sb[wid] = s; ssb[wid] = ss; }
    __syncthreads();
    if (tid == 0) {
        float S = 0.f, SS = 0.f;
        #pragma unroll
        for (int w = 0; w < 8; w++) { S += sb[w]; SS += ssb[w]; }
        float mu  = S * (1.f / 512.f);
        float var = SS * (1.f / 512.f) - mu * mu;
        stat[0] = mu;
        stat[1] = rsqrtf(var + 1e-5f);
    }
    __syncthreads();
    float mu = stat[0], rstd = stat[1];
    float2 gg = ((const float2*)g)[tid];
    float2 bb = ((const float2*)b)[tid];
    float ox = (v.x - mu) * rstd * gg.x + bb.x;
    float oy = (v.y - mu) * rstd * gg.y + bb.y;
    ((__nv_bfloat162*)(z + (size_t)l * C_))[tid] = __floats2bfloat162_rn(ox, oy);
}

// ---------------------------------------------------------------------------
// Segment boundaries from sorted row_index
// ---------------------------------------------------------------------------
__global__ void seg_kernel(const int* __restrict__ row, int* __restrict__ seg)
{
    int e = blockIdx.x * blockDim.x + threadIdx.x;
    if (e >= E_) return;
    int r  = row[e];
    int rp = (e == 0) ? -1 : row[e - 1];
    for (int l = rp + 1; l <= r; l++) seg[l] = e;
    if (e == E_ - 1) {
        for (int l = r + 1; l <= L_; l++) seg[l] = E_;
    }
}

// ---------------------------------------------------------------------------
// Sparse attention: one block (256 thr = 8 warps) per destination row.
// Output written as bf16 (consumed by Wo GEMM).
// ---------------------------------------------------------------------------
#define SMAX 256

__global__ __launch_bounds__(256) void attn_kernel(
    const float* __restrict__ Q, const float* __restrict__ K,
    const float* __restrict__ V, const float* __restrict__ bias,
    const int* __restrict__ col, const int* __restrict__ seg,
    bf16_t* __restrict__ out)
{
    __shared__ float sq[C_];
    __shared__ float sc[SMAX * H_];
    __shared__ float red[8 * C_];
    __shared__ float rm[H_], rs[H_], rf[H_];

    int l = blockIdx.x;
    int tid = threadIdx.x;
    int wid = tid >> 5, lane = tid & 31;
    int hb = lane >> 4;

    {
        const float2* qr = (const float2*)(Q + (size_t)l * C_);
        float2 t = qr[tid];
        t.x *= 0.125f; t.y *= 0.125f;
        ((float2*)sq)[tid] = t;
    }
    if (tid < H_) { rm[tid] = -1e30f; rs[tid] = 0.f; }
    __syncthreads();

    int e0 = seg[l], e1 = seg[l + 1];

    float acc[16];
    #pragma unroll
    for (int i = 0; i < 16; i++) acc[i] = 0.f;

    const float4* sq4 = (const float4*)sq;

    for (int c0 = e0; c0 < e1; c0 += SMAX) {
        int cn = min(SMAX, e1 - c0);

        for (int i = wid; i < cn; i += 8) {
            int e  = c0 + i;
            int cx = col[e];
            const float4* kp = (const float4*)(K + (size_t)cx * C_);
            float pd[4];
            #pragma unroll
            for (int r = 0; r < 4; r++) {
                float4 kk = kp[r * 32 + lane];
                float4 qq = sq4[r * 32 + lane];
                pd[r] = kk.x * qq.x + kk.y * qq.y + kk.z * qq.z + kk.w * qq.w;
            }
            #pragma unroll
            for (int m = 1; m < 16; m <<= 1) {
                #pragma unroll
                for (int r = 0; r < 4; r++)
                    pd[r] += __shfl_xor_sync(0xffffffffu, pd[r], m);
            }
            if ((lane & 15) == 0) {
                #pragma unroll
                for (int r = 0; r < 4; r++) {
                    int h = 2 * r + hb;
                    sc[i * H_ + h] = pd[r] + bias[(size_t)e * H_ + h];
                }
            }
        }
        __syncthreads();

        {
            int h = wid;
            float mx = -1e30f;
            for (int i = lane; i < cn; i += 32) mx = fmaxf(mx, sc[i * H_ + h]);
            #pragma unroll
            for (int m = 16; m >= 1; m >>= 1)
                mx = fmaxf(mx, __shfl_xor_sync(0xffffffffu, mx, m));
            float oldm = rm[h];
            float newm = fmaxf(oldm, mx);
            float fac  = __expf(oldm - newm);
            float ps = 0.f;
            for (int i = lane; i < cn; i += 32) {
                float p = __expf(sc[i * H_ + h] - newm);
                sc[i * H_ + h] = p;
                ps += p;
            }
            #pragma unroll
            for (int m = 16; m >= 1; m >>= 1)
                ps += __shfl_xor_sync(0xffffffffu, ps, m);
            if (lane == 0) {
                rs[h] = rs[h] * fac + ps;
                rm[h] = newm;
                rf[h] = fac;
            }
        }
        __syncthreads();

        #pragma unroll
        for (int r = 0; r < 4; r++) {
            float f = rf[2 * r + hb];
            acc[4 * r + 0] *= f; acc[4 * r + 1] *= f;
            acc[4 * r + 2] *= f; acc[4 * r + 3] *= f;
        }

        for (int i = wid; i < cn; i += 8) {
            int e  = c0 + i;
            int cx = col[e];
            const float4* vp = (const float4*)(V + (size_t)cx * C_);
            #pragma unroll
            for (int r = 0; r < 4; r++) {
                float p = sc[i * H_ + 2 * r + hb];
                float4 vv = vp[r * 32 + lane];
                acc[4 * r + 0] += p * vv.x;
                acc[4 * r + 1] += p * vv.y;
                acc[4 * r + 2] += p * vv.z;
                acc[4 * r + 3] += p * vv.w;
            }
        }
        __syncthreads();
    }

    #pragma unroll
    for (int r = 0; r < 4; r++) {
        float4 t = make_float4(acc[4 * r + 0], acc[4 * r + 1],
                               acc[4 * r + 2], acc[4 * r + 3]);
        ((float4*)red)[wid * 128 + r * 32 + lane] = t;
    }
    __syncthreads();
    #pragma unroll
    for (int it = 0; it < 2; it++) {
        int d = tid + it * 256;
        float s = 0.f;
        #pragma unroll
        for (int w = 0; w < 8; w++) s += red[w * C_ + d];
        float den = rs[d >> 6];
        float o = (den > 0.f) ? s / den : 0.f;
        out[(size_t)l * C_ + d] = __float2bfloat16_rn(o);
    }
}

// ---------------------------------------------------------------------------
// BF16 tensor-core GEMM: C = A(MxK) @ Bt^T + bias, optional epilogue.
// A: bf16 row-major [M][K].  Bt: bf16 [N][K] (pre-transposed weight).
// EPI: 0 = none, 1 = SiLU, 2 = + res.   OBF: 1 = bf16 output, 0 = f32.
// 128x128x32 tile, 256 threads = 8 warps (2x4), warptile 64x32 via
// mma.sync.m16n8k16 bf16, fp32 accumulate. Double-buffered smem.
// Smem row stride 40 bf16 (80 B): fragment LDS is bank-conflict-free.
// Requires M%128==0, N%128==0, K%32==0.
// ---------------------------------------------------------------------------
#define BKP 40

template <int EPI, int OBF>
__global__ __launch_bounds__(256, 2) void hgemm_kernel(
    const bf16_t* __restrict__ A, const bf16_t* __restrict__ Bt,
    const float* __restrict__ bias, const float* __restrict__ res,
    void* __restrict__ Cout, int M, int N, int K)
{
    __shared__ bf16_t As[2][128 * BKP];
    __shared__ bf16_t Bs[2][128 * BKP];

    int tid = threadIdx.x;
    int bx = blockIdx.x, by = blockIdx.y;
    int lane = tid & 31, wid = tid >> 5;
    int wm = (wid & 1) * 64, wn = (wid >> 1) * 32;
    int g = lane >> 2, t = lane & 3;

    int srow = tid >> 1;
    int skc  = (tid & 1) * 16;   // bf16 offset within the 32-wide k slab

    const uint4* Ag = (const uint4*)(A + (size_t)(by * 128 + srow) * K) + (skc >> 3);
    const uint4* Bg = (const uint4*)(Bt + (size_t)(bx * 128 + srow) * K) + (skc >> 3);

    float acc[4][4][4];
    #pragma unroll
    for (int mi = 0; mi < 4; mi++)
        #pragma unroll
        for (int ni = 0; ni < 4; ni++)
            #pragma unroll
            for (int r = 0; r < 4; r++) acc[mi][ni][r] = 0.f;

    // prologue: stage slab 0
    {
        uint4 a0 = Ag[0], a1 = Ag[1];
        uint4 b0 = Bg[0], b1 = Bg[1];
        *(uint4*)&As[0][srow * BKP + skc]     = a0;
        *(uint4*)&As[0][srow * BKP + skc + 8] = a1;
        *(uint4*)&Bs[0][srow * BKP + skc]     = b0;
        *(uint4*)&Bs[0][srow * BKP + skc + 8] = b1;
    }
    __syncthreads();

    int KT = K >> 5;   // K / 32
    int buf = 0;
    for (int kt = 0; kt < KT; kt++) {
        uint4 pa0, pa1, pb0, pb1;
        if (kt + 1 < KT) {
            pa0 = Ag[(kt + 1) * 4];
            pa1 = Ag[(kt + 1) * 4 + 1];
            pb0 = Bg[(kt + 1) * 4];
            pb1 = Bg[(kt + 1) * 4 + 1];
        }

        #pragma unroll
        for (int ks = 0; ks < 32; ks += 16) {
            unsigned af[4][4];
            unsigned bfr[4][2];
            #pragma unroll
            for (int mi = 0; mi < 4; mi++) {
                int base = (wm + mi * 16 + g) * BKP + ks + 2 * t;
                af[mi][0] = *(const unsigned*)&As[buf][base];
                af[mi][1] = *(const unsigned*)&As[buf][base + 8 * BKP];
                af[mi][2] = *(const unsigned*)&As[buf][base + 8];
                af[mi][3] = *(const unsigned*)&As[buf][base + 8 * BKP + 8];
            }
            #pragma unroll
            for (int ni = 0; ni < 4; ni++) {
                int cb = (wn + ni * 8 + g) * BKP + ks + 2 * t;
                bfr[ni][0] = *(const unsigned*)&Bs[buf][cb];
                bfr[ni][1] = *(const unsigned*)&Bs[buf][cb + 8];
            }
            #pragma unroll
            for (int mi = 0; mi < 4; mi++)
                #pragma unroll
                for (int ni = 0; ni < 4; ni++) {
                    asm volatile(
                        "mma.sync.aligned.m16n8k16.row.col.f32.bf16.bf16.f32 "
                        "{%0,%1,%2,%3}, {%4,%5,%6,%7}, {%8,%9}, {%0,%1,%2,%3};\n"
                        : "+f"(acc[mi][ni][0]), "+f"(acc[mi][ni][1]),
                          "+f"(acc[mi][ni][2]), "+f"(acc[mi][ni][3])
                        : "r"(af[mi][0]), "r"(af[mi][1]),
                          "r"(af[mi][2]), "r"(af[mi][3]),
                          "r"(bfr[ni][0]), "r"(bfr[ni][1]));
                }
        }

        if (kt + 1 < KT) {
            int nb = buf ^ 1;
            *(uint4*)&As[nb][srow * BKP + skc]     = pa0;
            *(uint4*)&As[nb][srow * BKP + skc + 8] = pa1;
            *(uint4*)&Bs[nb][srow * BKP + skc]     = pb0;
            *(uint4*)&Bs[nb][srow * BKP + skc + 8] = pb1;
            __syncthreads();
            buf = nb;
        }
    }

    // epilogue: c0,c1 -> (row g, cols 2t,2t+1); c2,c3 -> (row g+8, same cols)
    #pragma unroll
    for (int mi = 0; mi < 4; mi++) {
        #pragma unroll
        for (int ni = 0; ni < 4; ni++) {
            int col = bx * 128 + wn + ni * 8 + 2 * t;
            float2 bb = *(const float2*)&bias[col];
            #pragma unroll
            for (int h = 0; h < 2; h++) {
                int row = by * 128 + wm + mi * 16 + g + h * 8;
                float v0 = acc[mi][ni][2 * h + 0] + bb.x;
                float v1 = acc[mi][ni][2 * h + 1] + bb.y;
                if (EPI == 1) {
                    v0 = v0 / (1.f + __expf(-v0));
                    v1 = v1 / (1.f + __expf(-v1));
                }
                if (EPI == 2) {
                    float2 rr = *(const float2*)&res[(size_t)row * N + col];
                    v0 += rr.x; v1 += rr.y;
                }
                if (OBF) {
                    *(__nv_bfloat162*)((bf16_t*)Cout + (size_t)row * N + col) =
                        __floats2bfloat162_rn(v0, v1);
                } else {
                    *(float2*)((float*)Cout + (size_t)row * N + col) =
                        make_float2(v0, v1);
                }
            }
        }
    }
}

// ---------------------------------------------------------------------------
// Launch
// ---------------------------------------------------------------------------
extern "C" void kernel_launch(void* const* d_in, const int* in_sizes, int n_in,
                              void* d_out, int out_size)
{
    const float *x, *att_bias, *Wq, *bq, *Wk, *bk, *Wv, *bv, *Wo, *bo;
    const float *ln1g, *ln1b, *ln2g, *ln2b, *W1, *b1, *W2, *b2;
    const int *row, *col;

    if (in_sizes[1] == E_ * H_) {
        x        = (const float*)d_in[0];
        att_bias = (const float*)d_in[1];
        Wq = (const float*)d_in[2];  bq = (const float*)d_in[3];
        Wk = (const float*)d_in[4];  bk = (const float*)d_in[5];
        Wv = (const float*)d_in[6];  bv = (const float*)d_in[7];
        Wo = (const float*)d_in[8];  bo = (const float*)d_in[9];
        ln1g = (const float*)d_in[10]; ln1b = (const float*)d_in[11];
        ln2g = (const float*)d_in[12]; ln2b = (const float*)d_in[13];
        W1 = (const float*)d_in[14]; b1 = (const float*)d_in[15];
        W2 = (const float*)d_in[16]; b2 = (const float*)d_in[17];
        row = (const int*)d_in[18];  col = (const int*)d_in[19];
    } else {
        x   = (const float*)d_in[0];
        row = (const int*)d_in[1];
        col = (const int*)d_in[2];
        att_bias = (const float*)d_in[3];
        Wq = (const float*)d_in[4];  bq = (const float*)d_in[5];
        Wk = (const float*)d_in[6];  bk = (const float*)d_in[7];
        Wv = (const float*)d_in[8];  bv = (const float*)d_in[9];
        Wo = (const float*)d_in[10]; bo = (const float*)d_in[11];
        ln1g = (const float*)d_in[12]; ln1b = (const float*)d_in[13];
        ln2g = (const float*)d_in[14]; ln2b = (const float*)d_in[15];
        W1 = (const float*)d_in[16]; b1 = (const float*)d_in[17];
        W2 = (const float*)d_in[18]; b2 = (const float*)d_in[19];
    }

    bf16_t *pz, *pa, *ph, *pwq, *pwk, *pwv, *pwo, *pw1, *pw2;
    float *pq, *pk, *pv;
    int* pseg;
    cudaGetSymbolAddress((void**)&pz,  g_zb);
    cudaGetSymbolAddress((void**)&pq,  g_q);
    cudaGetSymbolAddress((void**)&pk,  g_k);
    cudaGetSymbolAddress((void**)&pv,  g_v);
    cudaGetSymbolAddress((void**)&pa,  g_attb);
    cudaGetSymbolAddress((void**)&ph,  g_hb);
    cudaGetSymbolAddress((void**)&pwq, g_wq);
    cudaGetSymbolAddress((void**)&pwk, g_wk);
    cudaGetSymbolAddress((void**)&pwv, g_wv);
    cudaGetSymbolAddress((void**)&pwo, g_wo);
    cudaGetSymbolAddress((void**)&pw1, g_w1);
    cudaGetSymbolAddress((void**)&pw2, g_w2);
    cudaGetSymbolAddress((void**)&pseg, g_seg);

    float* out = (float*)d_out;

    dim3 t32(32, 8);
    // 0. weight transpose+cast to bf16
    wcast_kernel<<<dim3(C_ / 32, C_ / 32), t32>>>(Wq, pwq, C_, C_);
    wcast_kernel<<<dim3(C_ / 32, C_ / 32), t32>>>(Wk, pwk, C_, C_);
    wcast_kernel<<<dim3(C_ / 32, C_ / 32), t32>>>(Wv, pwv, C_, C_);
    wcast_kernel<<<dim3(C_ / 32, C_ / 32), t32>>>(Wo, pwo, C_, C_);
    wcast_kernel<<<dim3(HID_ / 32, C_ / 32), t32>>>(W1, pw1, C_, HID_);
    wcast_kernel<<<dim3(C_ / 32, HID_ / 32), t32>>>(W2, pw2, HID_, C_);

    // 1. z = LN1(x)  (bf16)
    ln_kernel<<<L_, 256>>>(x, ln1g, ln1b, pz);
    // 2. segment boundaries
    seg_kernel<<<E_ / 256, 256>>>(row, pseg);
    // 3. q, k, v projections (bf16 tensor cores, f32 out)
    dim3 gC(C_ / 128, L_ / 128);
    hgemm_kernel<0, 0><<<gC, 256>>>(pz, pwq, bq, nullptr, pq, L_, C_, C_);
    hgemm_kernel<0, 0><<<gC, 256>>>(pz, pwk, bk, nullptr, pk, L_, C_, C_);
    hgemm_kernel<0, 0><<<gC, 256>>>(pz, pwv, bv, nullptr, pv, L_, C_, C_);
    // 4. sparse attention (f32 in, bf16 out)
    attn_kernel<<<L_, 256>>>(pq, pk, pv, att_bias, col, pseg, pa);
    // 5. out = x + att @ Wo + bo   (f32 out)
    hgemm_kernel<2, 0><<<gC, 256>>>(pa, pwo, bo, x, out, L_, C_, C_);
    // 6. z = LN2(out)  (bf16)
    ln_kernel<<<L_, 256>>>(out, ln2g, ln2b, pz);
    // 7. h = silu(z @ W1 + b1)  (bf16 out)
    dim3 gH(HID_ / 128, L_ / 128);
    hgemm_kernel<1, 1><<<gH, 256>>>(pz, pw1, b1, nullptr, ph, L_, HID_, C_);
    // 8. out = out + h @ W2 + b2  (f32 out, in-place residual)
    hgemm_kernel<2, 0><<<gC, 256>>>(ph, pw2, b2, out, out, L_, C_, HID_);
}

// round 5
// speedup vs baseline: 3.1891x; 1.1294x over previous
#include <cuda_runtime.h>
#include <cuda_bf16.h>
#include <math.h>
#include <cstdint>
#include <stdint.h>

// Problem constants
#define L_    32768
#define C_    512
#define H_    8
#define D_    64
#define E_    1048576
#define HID_  1024

typedef __nv_bfloat16 bf16_t;

// ---------------------------------------------------------------------------
// Scratch (device globals; no allocation allowed)
// ---------------------------------------------------------------------------
__device__ bf16_t g_zb[(size_t)L_ * C_];     // LN output (bf16, reused)
__device__ float  g_q[(size_t)L_ * C_];      // Q stays f32
__device__ bf16_t g_kb[(size_t)L_ * C_];     // K bf16 (gathered)
__device__ bf16_t g_vb[(size_t)L_ * C_];     // V bf16 (gathered)
__device__ bf16_t g_attb[(size_t)L_ * C_];   // attention output (bf16)
__device__ bf16_t g_hb[(size_t)L_ * HID_];   // MLP hidden (bf16)
__device__ bf16_t g_wq[C_ * C_], g_wk[C_ * C_], g_wv[C_ * C_], g_wo[C_ * C_];
__device__ bf16_t g_w1[C_ * HID_];           // W1^T  [HID][C]
__device__ bf16_t g_w2[C_ * HID_];           // W2^T  [C][HID]
__device__ int    g_seg[L_ + 1];

// ---------------------------------------------------------------------------
// Weight transpose + cast: W (K x N, f32) -> Wt (N x K, bf16)
// ---------------------------------------------------------------------------
__global__ __launch_bounds__(256) void wcast_kernel(
    const float* __restrict__ W, bf16_t* __restrict__ Wt, int K, int N)
{
    __shared__ float t[32][33];
    int n0 = blockIdx.x * 32, k0 = blockIdx.y * 32;
    int tx = threadIdx.x, ty = threadIdx.y;
    #pragma unroll
    for (int i = 0; i < 32; i += 8)
        t[ty + i][tx] = W[(size_t)(k0 + ty + i) * N + n0 + tx];
    __syncthreads();
    #pragma unroll
    for (int i = 0; i < 32; i += 8)
        Wt[(size_t)(n0 + ty + i) * K + k0 + tx] = __float2bfloat16_rn(t[tx][ty + i]);
}

// ---------------------------------------------------------------------------
// LayerNorm: one block per row, 256 threads, 2 floats/thread; bf16 output
// ---------------------------------------------------------------------------
__global__ __launch_bounds__(256) void ln_kernel(
    const float* __restrict__ x, const float* __restrict__ g,
    const float* __restrict__ b, bf16_t* __restrict__ z)
{
    int l = blockIdx.x, tid = threadIdx.x;
    const float2* xr = (const float2*)(x + (size_t)l * C_);
    float2 v = xr[tid];
    float s  = v.x + v.y;
    float ss = v.x * v.x + v.y * v.y;
    #pragma unroll
    for (int m = 16; m >= 1; m >>= 1) {
        s  += __shfl_xor_sync(0xffffffffu, s,  m);
        ss += __shfl_xor_sync(0xffffffffu, ss, m);
    }
    __shared__ float sb[8], ssb[8], stat[2];
    int wid = tid >> 5, lane = tid & 31;
    if (lane == 0) { sb[wid] = s; ssb[wid] = ss; }
    __syncthreads();
    if (tid == 0) {
        float S = 0.f, SS = 0.f;
        #pragma unroll
        for (int w = 0; w < 8; w++) { S += sb[w]; SS += ssb[w]; }
        float mu  = S * (1.f / 512.f);
        float var = SS * (1.f / 512.f) - mu * mu;
        stat[0] = mu;
        stat[1] = rsqrtf(var + 1e-5f);
    }
    __syncthreads();
    float mu = stat[0], rstd = stat[1];
    float2 gg = ((const float2*)g)[tid];
    float2 bb = ((const float2*)b)[tid];
    float ox = (v.x - mu) * rstd * gg.x + bb.x;
    float oy = (v.y - mu) * rstd * gg.y + bb.y;
    ((__nv_bfloat162*)(z + (size_t)l * C_))[tid] = __floats2bfloat162_rn(ox, oy);
}

// ---------------------------------------------------------------------------
// Segment boundaries from sorted row_index
// ---------------------------------------------------------------------------
__global__ void seg_kernel(const int* __restrict__ row, int* __restrict__ seg)
{
    int e = blockIdx.x * blockDim.x + threadIdx.x;
    if (e >= E_) return;
    int r  = row[e];
    int rp = (e == 0) ? -1 : row[e - 1];
    for (int l = rp + 1; l <= r; l++) seg[l] = e;
    if (e == E_ - 1) {
        for (int l = r + 1; l <= L_; l++) seg[l] = E_;
    }
}

// ---------------------------------------------------------------------------
// Sparse attention: one block (256 thr = 8 warps) per destination row.
// Q f32, K/V bf16 (halved gather traffic). Output bf16.
// Lane layout: lane covers 8 channels (one uint4 of bf16) at
// chan = (r*32+lane)*8, r = 0..1. Head of (r,lane) = r*4 + (lane>>3).
// ---------------------------------------------------------------------------
#define SMAX 256

__global__ __launch_bounds__(256) void attn_kernel(
    const float* __restrict__ Q, const bf16_t* __restrict__ K,
    const bf16_t* __restrict__ V, const float* __restrict__ bias,
    const int* __restrict__ col, const int* __restrict__ seg,
    bf16_t* __restrict__ out)
{
    __shared__ float sq[C_];
    __shared__ float sc[SMAX * H_];
    __shared__ float red[8 * C_];
    __shared__ float rm[H_], rs[H_], rf[H_];

    int l = blockIdx.x;
    int tid = threadIdx.x;
    int wid = tid >> 5, lane = tid & 31;
    int hsub = lane >> 3;   // head sub-index within r-chunk (0..3)

    {
        const float2* qr = (const float2*)(Q + (size_t)l * C_);
        float2 t = qr[tid];
        t.x *= 0.125f; t.y *= 0.125f;
        ((float2*)sq)[tid] = t;
    }
    if (tid < H_) { rm[tid] = -1e30f; rs[tid] = 0.f; }
    __syncthreads();

    int e0 = seg[l], e1 = seg[l + 1];

    float acc[16];
    #pragma unroll
    for (int i = 0; i < 16; i++) acc[i] = 0.f;

    const float4* sq4 = (const float4*)sq;

    for (int c0 = e0; c0 < e1; c0 += SMAX) {
        int cn = min(SMAX, e1 - c0);

        // ---- scores
        for (int i = wid; i < cn; i += 8) {
            int e  = c0 + i;
            int cx = col[e];
            const uint4* kp = (const uint4*)(K + (size_t)cx * C_);
            float pd[2];
            #pragma unroll
            for (int r = 0; r < 2; r++) {
                uint4 kk = kp[r * 32 + lane];
                const __nv_bfloat162* h2 = (const __nv_bfloat162*)&kk;
                float2 f0 = __bfloat1622float2(h2[0]);
                float2 f1 = __bfloat1622float2(h2[1]);
                float2 f2 = __bfloat1622float2(h2[2]);
                float2 f3 = __bfloat1622float2(h2[3]);
                const float4* qq = sq4 + (size_t)(r * 32 + lane) * 2;
                float4 q0 = qq[0], q1 = qq[1];
                pd[r] = q0.x * f0.x + q0.y * f0.y + q0.z * f1.x + q0.w * f1.y
                      + q1.x * f2.x + q1.y * f2.y + q1.z * f3.x + q1.w * f3.y;
            }
            #pragma unroll
            for (int m = 1; m < 8; m <<= 1) {
                #pragma unroll
                for (int r = 0; r < 2; r++)
                    pd[r] += __shfl_xor_sync(0xffffffffu, pd[r], m);
            }
            if ((lane & 7) == 0) {
                #pragma unroll
                for (int r = 0; r < 2; r++) {
                    int h = r * 4 + hsub;
                    sc[i * H_ + h] = pd[r] + bias[(size_t)e * H_ + h];
                }
            }
        }
        __syncthreads();

        // ---- per-head running max / sum: warp `wid` owns head `wid`
        {
            int h = wid;
            float mx = -1e30f;
            for (int i = lane; i < cn; i += 32) mx = fmaxf(mx, sc[i * H_ + h]);
            #pragma unroll
            for (int m = 16; m >= 1; m >>= 1)
                mx = fmaxf(mx, __shfl_xor_sync(0xffffffffu, mx, m));
            float oldm = rm[h];
            float newm = fmaxf(oldm, mx);
            float fac  = __expf(oldm - newm);
            float ps = 0.f;
            for (int i = lane; i < cn; i += 32) {
                float p = __expf(sc[i * H_ + h] - newm);
                sc[i * H_ + h] = p;
                ps += p;
            }
            #pragma unroll
            for (int m = 16; m >= 1; m >>= 1)
                ps += __shfl_xor_sync(0xffffffffu, ps, m);
            if (lane == 0) {
                rs[h] = rs[h] * fac + ps;
                rm[h] = newm;
                rf[h] = fac;
            }
        }
        __syncthreads();

        // ---- rescale accumulators
        #pragma unroll
        for (int r = 0; r < 2; r++) {
            float f = rf[r * 4 + hsub];
            #pragma unroll
            for (int j = 0; j < 8; j++) acc[r * 8 + j] *= f;
        }

        // ---- weighted V accumulation
        for (int i = wid; i < cn; i += 8) {
            int e  = c0 + i;
            int cx = col[e];
            const uint4* vp = (const uint4*)(V + (size_t)cx * C_);
            #pragma unroll
            for (int r = 0; r < 2; r++) {
                float p = sc[i * H_ + r * 4 + hsub];
                uint4 vv = vp[r * 32 + lane];
                const __nv_bfloat162* h2 = (const __nv_bfloat162*)&vv;
                float2 f0 = __bfloat1622float2(h2[0]);
                float2 f1 = __bfloat1622float2(h2[1]);
                float2 f2 = __bfloat1622float2(h2[2]);
                float2 f3 = __bfloat1622float2(h2[3]);
                acc[r * 8 + 0] += p * f0.x;
                acc[r * 8 + 1] += p * f0.y;
                acc[r * 8 + 2] += p * f1.x;
                acc[r * 8 + 3] += p * f1.y;
                acc[r * 8 + 4] += p * f2.x;
                acc[r * 8 + 5] += p * f2.y;
                acc[r * 8 + 6] += p * f3.x;
                acc[r * 8 + 7] += p * f3.y;
            }
        }
        __syncthreads();
    }

    // ---- cross-warp reduce + normalize
    #pragma unroll
    for (int r = 0; r < 2; r++) {
        float4 t0 = make_float4(acc[r*8+0], acc[r*8+1], acc[r*8+2], acc[r*8+3]);
        float4 t1 = make_float4(acc[r*8+4], acc[r*8+5], acc[r*8+6], acc[r*8+7]);
        ((float4*)red)[wid * 128 + (r * 32 + lane) * 2 + 0] = t0;
        ((float4*)red)[wid * 128 + (r * 32 + lane) * 2 + 1] = t1;
    }
    __syncthreads();
    #pragma unroll
    for (int it = 0; it < 2; it++) {
        int d = tid + it * 256;
        float s = 0.f;
        #pragma unroll
        for (int w = 0; w < 8; w++) s += red[w * C_ + d];
        float den = rs[d >> 6];
        float o = (den > 0.f) ? s / den : 0.f;
        out[(size_t)l * C_ + d] = __float2bfloat16_rn(o);
    }
}

// ---------------------------------------------------------------------------
// BF16 tensor-core GEMM with cp.async 3-stage pipeline.
// C = A(MxK) @ Bt^T + bias, A bf16 [M][K], Bt bf16 [N][K].
// EPI: 0 none, 1 SiLU, 2 +res.  OBF: 1 bf16 out, 0 f32 out.
// 128x128x32 tile, 256 threads, warptile 64x32, mma.m16n8k16.
// Dynamic smem: 3 stages x (As+Bs) x 128 x BKP bf16 = 61440 B.
// ---------------------------------------------------------------------------
#define BKP 40
#define STG 3

__device__ __forceinline__ void cp16(uint32_t s, const void* g) {
    asm volatile("cp.async.cg.shared.global [%0], [%1], 16;\n"
                 :: "r"(s), "l"(g));
}

template <int EPI, int OBF>
__global__ __launch_bounds__(256, 2) void hgemm_kernel(
    const bf16_t* __restrict__ A, const bf16_t* __restrict__ Bt,
    const float* __restrict__ bias, const float* __restrict__ res,
    void* __restrict__ Cout, int M, int N, int K)
{
    extern __shared__ bf16_t smem[];
    bf16_t* As = smem;                       // [STG][128*BKP]
    bf16_t* Bs = smem + STG * 128 * BKP;

    int tid = threadIdx.x;
    int bx = blockIdx.x, by = blockIdx.y;
    int lane = tid & 31, wid = tid >> 5;
    int wm = (wid & 1) * 64, wn = (wid >> 1) * 32;
    int g = lane >> 2, t = lane & 3;

    int srow = tid >> 1;
    int skc  = (tid & 1) * 16;

    const bf16_t* Agp = A  + (size_t)(by * 128 + srow) * K + skc;
    const bf16_t* Bgp = Bt + (size_t)(bx * 128 + srow) * K + skc;
    uint32_t sa = (uint32_t)__cvta_generic_to_shared(As + srow * BKP + skc);
    uint32_t sb = (uint32_t)__cvta_generic_to_shared(Bs + srow * BKP + skc);
    const uint32_t stgb = 128 * BKP * 2;   // bytes per stage

    float acc[4][4][4];
    #pragma unroll
    for (int mi = 0; mi < 4; mi++)
        #pragma unroll
        for (int ni = 0; ni < 4; ni++)
            #pragma unroll
            for (int r = 0; r < 4; r++) acc[mi][ni][r] = 0.f;

    int KT = K >> 5;

    // prologue: issue slabs 0 and 1
    #pragma unroll
    for (int s = 0; s < 2; s++) {
        cp16(sa + s * stgb,      Agp + s * 32);
        cp16(sa + s * stgb + 16, Agp + s * 32 + 8);
        cp16(sb + s * stgb,      Bgp + s * 32);
        cp16(sb + s * stgb + 16, Bgp + s * 32 + 8);
        asm volatile("cp.async.commit_group;\n");
    }

    int buf = 0;
    for (int kt = 0; kt < KT; kt++) {
        if (kt + 1 < KT) {
            asm volatile("cp.async.wait_group 1;\n");
        } else {
            asm volatile("cp.async.wait_group 0;\n");
        }
        __syncthreads();

        const bf16_t* Ab = As + buf * 128 * BKP;
        const bf16_t* Bb = Bs + buf * 128 * BKP;

        #pragma unroll
        for (int ks = 0; ks < 32; ks += 16) {
            unsigned af[4][4];
            unsigned bfr[4][2];
            #pragma unroll
            for (int mi = 0; mi < 4; mi++) {
                int base = (wm + mi * 16 + g) * BKP + ks + 2 * t;
                af[mi][0] = *(const unsigned*)&Ab[base];
                af[mi][1] = *(const unsigned*)&Ab[base + 8 * BKP];
                af[mi][2] = *(const unsigned*)&Ab[base + 8];
                af[mi][3] = *(const unsigned*)&Ab[base + 8 * BKP + 8];
            }
            #pragma unroll
            for (int ni = 0; ni < 4; ni++) {
                int cb = (wn + ni * 8 + g) * BKP + ks + 2 * t;
                bfr[ni][0] = *(const unsigned*)&Bb[cb];
                bfr[ni][1] = *(const unsigned*)&Bb[cb + 8];
            }
            #pragma unroll
            for (int mi = 0; mi < 4; mi++)
                #pragma unroll
                for (int ni = 0; ni < 4; ni++) {
                    asm volatile(
                        "mma.sync.aligned.m16n8k16.row.col.f32.bf16.bf16.f32 "
                        "{%0,%1,%2,%3}, {%4,%5,%6,%7}, {%8,%9}, {%0,%1,%2,%3};\n"
                        : "+f"(acc[mi][ni][0]), "+f"(acc[mi][ni][1]),
                          "+f"(acc[mi][ni][2]), "+f"(acc[mi][ni][3])
                        : "r"(af[mi][0]), "r"(af[mi][1]),
                          "r"(af[mi][2]), "r"(af[mi][3]),
                          "r"(bfr[ni][0]), "r"(bfr[ni][1]));
                }
        }

        if (kt + 2 < KT) {
            int s = (kt + 2) % STG;
            cp16(sa + s * stgb,      Agp + (kt + 2) * 32);
            cp16(sa + s * stgb + 16, Agp + (kt + 2) * 32 + 8);
            cp16(sb + s * stgb,      Bgp + (kt + 2) * 32);
            cp16(sb + s * stgb + 16, Bgp + (kt + 2) * 32 + 8);
            asm volatile("cp.async.commit_group;\n");
        }
        buf = (buf + 1) % STG;
    }

    // epilogue
    #pragma unroll
    for (int mi = 0; mi < 4; mi++) {
        #pragma unroll
        for (int ni = 0; ni < 4; ni++) {
            int col = bx * 128 + wn + ni * 8 + 2 * t;
            float2 bb = *(const float2*)&bias[col];
            #pragma unroll
            for (int h = 0; h < 2; h++) {
                int row = by * 128 + wm + mi * 16 + g + h * 8;
                float v0 = acc[mi][ni][2 * h + 0] + bb.x;
                float v1 = acc[mi][ni][2 * h + 1] + bb.y;
                if (EPI == 1) {
                    v0 = v0 / (1.f + __expf(-v0));
                    v1 = v1 / (1.f + __expf(-v1));
                }
                if (EPI == 2) {
                    float2 rr = *(const float2*)&res[(size_t)row * N + col];
                    v0 += rr.x; v1 += rr.y;
                }
                if (OBF) {
                    *(__nv_bfloat162*)((bf16_t*)Cout + (size_t)row * N + col) =
                        __floats2bfloat162_rn(v0, v1);
                } else {
                    *(float2*)((float*)Cout + (size_t)row * N + col) =
                        make_float2(v0, v1);
                }
            }
        }
    }
}

// ---------------------------------------------------------------------------
// Launch
// ---------------------------------------------------------------------------
#define HS_BYTES (2 * STG * 128 * BKP * 2)

extern "C" void kernel_launch(void* const* d_in, const int* in_sizes, int n_in,
                              void* d_out, int out_size)
{
    const float *x, *att_bias, *Wq, *bq, *Wk, *bk, *Wv, *bv, *Wo, *bo;
    const float *ln1g, *ln1b, *ln2g, *ln2b, *W1, *b1, *W2, *b2;
    const int *row, *col;

    if (in_sizes[1] == E_ * H_) {
        x        = (const float*)d_in[0];
        att_bias = (const float*)d_in[1];
        Wq = (const float*)d_in[2];  bq = (const float*)d_in[3];
        Wk = (const float*)d_in[4];  bk = (const float*)d_in[5];
        Wv = (const float*)d_in[6];  bv = (const float*)d_in[7];
        Wo = (const float*)d_in[8];  bo = (const float*)d_in[9];
        ln1g = (const float*)d_in[10]; ln1b = (const float*)d_in[11];
        ln2g = (const float*)d_in[12]; ln2b = (const float*)d_in[13];
        W1 = (const float*)d_in[14]; b1 = (const float*)d_in[15];
        W2 = (const float*)d_in[16]; b2 = (const float*)d_in[17];
        row = (const int*)d_in[18];  col = (const int*)d_in[19];
    } else {
        x   = (const float*)d_in[0];
        row = (const int*)d_in[1];
        col = (const int*)d_in[2];
        att_bias = (const float*)d_in[3];
        Wq = (const float*)d_in[4];  bq = (const float*)d_in[5];
        Wk = (const float*)d_in[6];  bk = (const float*)d_in[7];
        Wv = (const float*)d_in[8];  bv = (const float*)d_in[9];
        Wo = (const float*)d_in[10]; bo = (const float*)d_in[11];
        ln1g = (const float*)d_in[12]; ln1b = (const float*)d_in[13];
        ln2g = (const float*)d_in[14]; ln2b = (const float*)d_in[15];
        W1 = (const float*)d_in[16]; b1 = (const float*)d_in[17];
        W2 = (const float*)d_in[18]; b2 = (const float*)d_in[19];
    }

    bf16_t *pz, *pkb, *pvb, *pa, *ph, *pwq, *pwk, *pwv, *pwo, *pw1, *pw2;
    float *pq;
    int* pseg;
    cudaGetSymbolAddress((void**)&pz,  g_zb);
    cudaGetSymbolAddress((void**)&pq,  g_q);
    cudaGetSymbolAddress((void**)&pkb, g_kb);
    cudaGetSymbolAddress((void**)&pvb, g_vb);
    cudaGetSymbolAddress((void**)&pa,  g_attb);
    cudaGetSymbolAddress((void**)&ph,  g_hb);
    cudaGetSymbolAddress((void**)&pwq, g_wq);
    cudaGetSymbolAddress((void**)&pwk, g_wk);
    cudaGetSymbolAddress((void**)&pwv, g_wv);
    cudaGetSymbolAddress((void**)&pwo, g_wo);
    cudaGetSymbolAddress((void**)&pw1, g_w1);
    cudaGetSymbolAddress((void**)&pw2, g_w2);
    cudaGetSymbolAddress((void**)&pseg, g_seg);

    // opt-in dynamic smem > 48KB (host-side attribute set; not a stream op)
    static bool attr_done = false;
    if (!attr_done) {
        cudaFuncSetAttribute(hgemm_kernel<0,0>, cudaFuncAttributeMaxDynamicSharedMemorySize, HS_BYTES);
        cudaFuncSetAttribute(hgemm_kernel<0,1>, cudaFuncAttributeMaxDynamicSharedMemorySize, HS_BYTES);
        cudaFuncSetAttribute(hgemm_kernel<2,0>, cudaFuncAttributeMaxDynamicSharedMemorySize, HS_BYTES);
        cudaFuncSetAttribute(hgemm_kernel<1,1>, cudaFuncAttributeMaxDynamicSharedMemorySize, HS_BYTES);
        attr_done = true;
    }

    float* out = (float*)d_out;

    dim3 t32(32, 8);
    // 0. weight transpose+cast to bf16
    wcast_kernel<<<dim3(C_ / 32, C_ / 32), t32>>>(Wq, pwq, C_, C_);
    wcast_kernel<<<dim3(C_ / 32, C_ / 32), t32>>>(Wk, pwk, C_, C_);
    wcast_kernel<<<dim3(C_ / 32, C_ / 32), t32>>>(Wv, pwv, C_, C_);
    wcast_kernel<<<dim3(C_ / 32, C_ / 32), t32>>>(Wo, pwo, C_, C_);
    wcast_kernel<<<dim3(HID_ / 32, C_ / 32), t32>>>(W1, pw1, C_, HID_);
    wcast_kernel<<<dim3(C_ / 32, HID_ / 32), t32>>>(W2, pw2, HID_, C_);

    // 1. z = LN1(x)  (bf16)
    ln_kernel<<<L_, 256>>>(x, ln1g, ln1b, pz);
    // 2. segment boundaries
    seg_kernel<<<E_ / 256, 256>>>(row, pseg);
    // 3. q (f32), k, v (bf16) projections
    dim3 gC(C_ / 128, L_ / 128);
    hgemm_kernel<0, 0><<<gC, 256, HS_BYTES>>>(pz, pwq, bq, nullptr, pq, L_, C_, C_);
    hgemm_kernel<0, 1><<<gC, 256, HS_BYTES>>>(pz, pwk, bk, nullptr, pkb, L_, C_, C_);
    hgemm_kernel<0, 1><<<gC, 256, HS_BYTES>>>(pz, pwv, bv, nullptr, pvb, L_, C_, C_);
    // 4. sparse attention (bf16 K/V gather, bf16 out)
    attn_kernel<<<L_, 256>>>(pq, pkb, pvb, att_bias, col, pseg, pa);
    // 5. out = x + att @ Wo + bo   (f32 out)
    hgemm_kernel<2, 0><<<gC, 256, HS_BYTES>>>(pa, pwo, bo, x, out, L_, C_, C_);
    // 6. z = LN2(out)  (bf16)
    ln_kernel<<<L_, 256>>>(out, ln2g, ln2b, pz);
    // 7. h = silu(z @ W1 + b1)  (bf16 out)
    dim3 gH(HID_ / 128, L_ / 128);
    hgemm_kernel<1, 1><<<gH, 256, HS_BYTES>>>(pz, pw1, b1, nullptr, ph, L_, HID_, C_);
    // 8. out = out + h @ W2 + b2  (f32 out, in-place residual)
    hgemm_kernel<2, 0><<<gC, 256, HS_BYTES>>>(ph, pw2, b2, out, out, L_, C_, HID_);
}

// round 7
// speedup vs baseline: 3.4402x; 1.0787x over previous
#include <cuda_runtime.h>
#include <cuda_bf16.h>
#include <math.h>
#include <cstdint>
#include <stdint.h>

// Problem constants
#define L_    32768
#define C_    512
#define H_    8
#define D_    64
#define E_    1048576
#define HID_  1024

typedef __nv_bfloat16 bf16_t;

// ---------------------------------------------------------------------------
// Scratch (device globals; no allocation allowed)
// ---------------------------------------------------------------------------
__device__ bf16_t g_zb[(size_t)L_ * C_];     // LN output (bf16, reused)
__device__ float  g_q[(size_t)L_ * C_];      // Q f32
__device__ bf16_t g_kb[(size_t)L_ * C_];     // K bf16
__device__ bf16_t g_vb[(size_t)L_ * C_];     // V bf16
__device__ bf16_t g_attb[(size_t)L_ * C_];   // attention output (bf16)
__device__ bf16_t g_hb[(size_t)L_ * HID_];   // MLP hidden (bf16)
__device__ bf16_t g_wq[C_ * C_], g_wk[C_ * C_], g_wv[C_ * C_], g_wo[C_ * C_];
__device__ bf16_t g_w1[C_ * HID_];           // W1^T  [HID][C]
__device__ bf16_t g_w2[C_ * HID_];           // W2^T  [C][HID]
__device__ int    g_seg[L_ + 1];

// ---------------------------------------------------------------------------
// Weight transpose + cast: W (K x N, f32) -> Wt (N x K, bf16)
// ---------------------------------------------------------------------------
__global__ __launch_bounds__(256) void wcast_kernel(
    const float* __restrict__ W, bf16_t* __restrict__ Wt, int K, int N)
{
    __shared__ float t[32][33];
    int n0 = blockIdx.x * 32, k0 = blockIdx.y * 32;
    int tx = threadIdx.x, ty = threadIdx.y;
    #pragma unroll
    for (int i = 0; i < 32; i += 8)
        t[ty + i][tx] = W[(size_t)(k0 + ty + i) * N + n0 + tx];
    __syncthreads();
    #pragma unroll
    for (int i = 0; i < 32; i += 8)
        Wt[(size_t)(n0 + ty + i) * K + k0 + tx] = __float2bfloat16_rn(t[tx][ty + i]);
}

// ---------------------------------------------------------------------------
// LayerNorm: one block (128 thr) per row, float4 per thread; bf16 output
// ---------------------------------------------------------------------------
__global__ __launch_bounds__(128) void ln_kernel(
    const float* __restrict__ x, const float* __restrict__ g,
    const float* __restrict__ b, bf16_t* __restrict__ z)
{
    int l = blockIdx.x, tid = threadIdx.x;
    float4 v = ((const float4*)(x + (size_t)l * C_))[tid];
    float s  = v.x + v.y + v.z + v.w;
    float ss = v.x * v.x + v.y * v.y + v.z * v.z + v.w * v.w;
    #pragma unroll
    for (int m = 16; m >= 1; m >>= 1) {
        s  += __shfl_xor_sync(0xffffffffu, s,  m);
        ss += __shfl_xor_sync(0xffffffffu, ss, m);
    }
    __shared__ float sb[4], ssb[4], stat[2];
    int wid = tid >> 5, lane = tid & 31;
    if (lane == 0) { sb[wid] = s; ssb[wid] = ss; }
    __syncthreads();
    if (tid == 0) {
        float S = sb[0] + sb[1] + sb[2] + sb[3];
        float SS = ssb[0] + ssb[1] + ssb[2] + ssb[3];
        float mu  = S * (1.f / 512.f);
        float var = SS * (1.f / 512.f) - mu * mu;
        stat[0] = mu;
        stat[1] = rsqrtf(var + 1e-5f);
    }
    __syncthreads();
    float mu = stat[0], rstd = stat[1];
    float4 gg = ((const float4*)g)[tid];
    float4 bb = ((const float4*)b)[tid];
    float o0 = (v.x - mu) * rstd * gg.x + bb.x;
    float o1 = (v.y - mu) * rstd * gg.y + bb.y;
    float o2 = (v.z - mu) * rstd * gg.z + bb.z;
    float o3 = (v.w - mu) * rstd * gg.w + bb.w;
    __nv_bfloat162 p0 = __floats2bfloat162_rn(o0, o1);
    __nv_bfloat162 p1 = __floats2bfloat162_rn(o2, o3);
    uint2 pk;
    pk.x = *(unsigned*)&p0;
    pk.y = *(unsigned*)&p1;
    ((uint2*)(z + (size_t)l * C_))[tid] = pk;
}

// ---------------------------------------------------------------------------
// Segment boundaries from sorted row_index
// ---------------------------------------------------------------------------
__global__ void seg_kernel(const int* __restrict__ row, int* __restrict__ seg)
{
    int e = blockIdx.x * blockDim.x + threadIdx.x;
    if (e >= E_) return;
    int r  = row[e];
    int rp = (e == 0) ? -1 : row[e - 1];
    for (int l = rp + 1; l <= r; l++) seg[l] = e;
    if (e == E_ - 1) {
        for (int l = r + 1; l <= L_; l++) seg[l] = E_;
    }
}

// ---------------------------------------------------------------------------
// Sparse attention: one block (256 thr = 8 warps) per destination row.
// Q f32, K/V bf16. Output bf16.
// ---------------------------------------------------------------------------
#define SMAX 256

__global__ __launch_bounds__(256) void attn_kernel(
    const float* __restrict__ Q, const bf16_t* __restrict__ K,
    const bf16_t* __restrict__ V, const float* __restrict__ bias,
    const int* __restrict__ col, const int* __restrict__ seg,
    bf16_t* __restrict__ out)
{
    __shared__ float sq[C_];
    __shared__ float sc[SMAX * H_];
    __shared__ float red[8 * C_];
    __shared__ float rm[H_], rs[H_], rf[H_];

    int l = blockIdx.x;
    int tid = threadIdx.x;
    int wid = tid >> 5, lane = tid & 31;
    int hsub = lane >> 3;

    {
        const float2* qr = (const float2*)(Q + (size_t)l * C_);
        float2 t = qr[tid];
        t.x *= 0.125f; t.y *= 0.125f;
        ((float2*)sq)[tid] = t;
    }
    if (tid < H_) { rm[tid] = -1e30f; rs[tid] = 0.f; }
    __syncthreads();

    int e0 = seg[l], e1 = seg[l + 1];

    float acc[16];
    #pragma unroll
    for (int i = 0; i < 16; i++) acc[i] = 0.f;

    const float4* sq4 = (const float4*)sq;

    for (int c0 = e0; c0 < e1; c0 += SMAX) {
        int cn = min(SMAX, e1 - c0);

        for (int i = wid; i < cn; i += 8) {
            int e  = c0 + i;
            int cx = col[e];
            const uint4* kp = (const uint4*)(K + (size_t)cx * C_);
            float pd[2];
            #pragma unroll
            for (int r = 0; r < 2; r++) {
                uint4 kk = kp[r * 32 + lane];
                const __nv_bfloat162* h2 = (const __nv_bfloat162*)&kk;
                float2 f0 = __bfloat1622float2(h2[0]);
                float2 f1 = __bfloat1622float2(h2[1]);
                float2 f2 = __bfloat1622float2(h2[2]);
                float2 f3 = __bfloat1622float2(h2[3]);
                const float4* qq = sq4 + (size_t)(r * 32 + lane) * 2;
                float4 q0 = qq[0], q1 = qq[1];
                pd[r] = q0.x * f0.x + q0.y * f0.y + q0.z * f1.x + q0.w * f1.y
                      + q1.x * f2.x + q1.y * f2.y + q1.z * f3.x + q1.w * f3.y;
            }
            #pragma unroll
            for (int m = 1; m < 8; m <<= 1) {
                #pragma unroll
                for (int r = 0; r < 2; r++)
                    pd[r] += __shfl_xor_sync(0xffffffffu, pd[r], m);
            }
            if ((lane & 7) == 0) {
                #pragma unroll
                for (int r = 0; r < 2; r++) {
                    int h = r * 4 + hsub;
                    sc[i * H_ + h] = pd[r] + bias[(size_t)e * H_ + h];
                }
            }
        }
        __syncthreads();

        {
            int h = wid;
            float mx = -1e30f;
            for (int i = lane; i < cn; i += 32) mx = fmaxf(mx, sc[i * H_ + h]);
            #pragma unroll
            for (int m = 16; m >= 1; m >>= 1)
                mx = fmaxf(mx, __shfl_xor_sync(0xffffffffu, mx, m));
            float oldm = rm[h];
            float newm = fmaxf(oldm, mx);
            float fac  = __expf(oldm - newm);
            float ps = 0.f;
            for (int i = lane; i < cn; i += 32) {
                float p = __expf(sc[i * H_ + h] - newm);
                sc[i * H_ + h] = p;
                ps += p;
            }
            #pragma unroll
            for (int m = 16; m >= 1; m >>= 1)
                ps += __shfl_xor_sync(0xffffffffu, ps, m);
            if (lane == 0) {
                rs[h] = rs[h] * fac + ps;
                rm[h] = newm;
                rf[h] = fac;
            }
        }
        __syncthreads();

        #pragma unroll
        for (int r = 0; r < 2; r++) {
            float f = rf[r * 4 + hsub];
            #pragma unroll
            for (int j = 0; j < 8; j++) acc[r * 8 + j] *= f;
        }

        for (int i = wid; i < cn; i += 8) {
            int e  = c0 + i;
            int cx = col[e];
            const uint4* vp = (const uint4*)(V + (size_t)cx * C_);
            #pragma unroll
            for (int r = 0; r < 2; r++) {
                float p = sc[i * H_ + r * 4 + hsub];
                uint4 vv = vp[r * 32 + lane];
                const __nv_bfloat162* h2 = (const __nv_bfloat162*)&vv;
                float2 f0 = __bfloat1622float2(h2[0]);
                float2 f1 = __bfloat1622float2(h2[1]);
                float2 f2 = __bfloat1622float2(h2[2]);
                float2 f3 = __bfloat1622float2(h2[3]);
                acc[r * 8 + 0] += p * f0.x;
                acc[r * 8 + 1] += p * f0.y;
                acc[r * 8 + 2] += p * f1.x;
                acc[r * 8 + 3] += p * f1.y;
                acc[r * 8 + 4] += p * f2.x;
                acc[r * 8 + 5] += p * f2.y;
                acc[r * 8 + 6] += p * f3.x;
                acc[r * 8 + 7] += p * f3.y;
            }
        }
        __syncthreads();
    }

    #pragma unroll
    for (int r = 0; r < 2; r++) {
        float4 t0 = make_float4(acc[r*8+0], acc[r*8+1], acc[r*8+2], acc[r*8+3]);
        float4 t1 = make_float4(acc[r*8+4], acc[r*8+5], acc[r*8+6], acc[r*8+7]);
        ((float4*)red)[wid * 128 + (r * 32 + lane) * 2 + 0] = t0;
        ((float4*)red)[wid * 128 + (r * 32 + lane) * 2 + 1] = t1;
    }
    __syncthreads();
    #pragma unroll
    for (int it = 0; it < 2; it++) {
        int d = tid + it * 256;
        float s = 0.f;
        #pragma unroll
        for (int w = 0; w < 8; w++) s += red[w * C_ + d];
        float den = rs[d >> 6];
        float o = (den > 0.f) ? s / den : 0.f;
        out[(size_t)l * C_ + d] = __float2bfloat16_rn(o);
    }
}

// ---------------------------------------------------------------------------
// BF16 tensor-core GEMM with cp.async 3-stage pipeline + ldmatrix fragments.
// C = A(MxK) @ Bt^T + bias, A bf16 [M][K], Bt bf16 [N][K].
// EPI: 0 none, 1 SiLU, 2 +res.  OBF: 1 bf16 out, 0 f32 out.
// 128x128x32 tile, 256 threads, warptile 64x32, mma.m16n8k16.
// Dynamic smem: 3 stages x (As+Bs) x 128 x BKP bf16 = 61440 B.
// ---------------------------------------------------------------------------
#define BKP 40
#define STG 3

__device__ __forceinline__ void cp16(uint32_t s, const void* g) {
    asm volatile("cp.async.cg.shared.global [%0], [%1], 16;\n"
                 :: "r"(s), "l"(g));
}

#define LDMX4(r0, r1, r2, r3, addr) \
    asm volatile("ldmatrix.sync.aligned.m8n8.x4.shared.b16 {%0,%1,%2,%3}, [%4];" \
                 : "=r"(r0), "=r"(r1), "=r"(r2), "=r"(r3) : "r"(addr))

template <int EPI, int OBF>
__global__ __launch_bounds__(256, 2) void hgemm_kernel(
    const bf16_t* __restrict__ A, const bf16_t* __restrict__ Bt,
    const float* __restrict__ bias, const float* __restrict__ res,
    void* __restrict__ Cout, int M, int N, int K)
{
    extern __shared__ bf16_t smem[];
    bf16_t* As = smem;                       // [STG][128*BKP]
    bf16_t* Bs = smem + STG * 128 * BKP;

    int tid = threadIdx.x;
    int bx = blockIdx.x, by = blockIdx.y;
    int lane = tid & 31, wid = tid >> 5;
    int wm = (wid & 1) * 64, wn = (wid >> 1) * 32;
    int g = lane >> 2, t = lane & 3;

    int srow = tid >> 1;
    int skc  = (tid & 1) * 16;

    const bf16_t* Agp = A  + (size_t)(by * 128 + srow) * K + skc;
    const bf16_t* Bgp = Bt + (size_t)(bx * 128 + srow) * K + skc;
    uint32_t sa = (uint32_t)__cvta_generic_to_shared(As + srow * BKP + skc);
    uint32_t sb = (uint32_t)__cvta_generic_to_shared(Bs + srow * BKP + skc);
    const uint32_t stgb = 128 * BKP * 2;   // bytes per stage

    // ldmatrix per-lane address offsets (bytes, within a stage)
    uint32_t uA = (uint32_t)__cvta_generic_to_shared(As);
    uint32_t uB = (uint32_t)__cvta_generic_to_shared(Bs);
    int lq = lane >> 3, lr = lane & 7;
    // A x4: [rows0-7,k0][rows8-15,k0][rows0-7,k8][rows8-15,k8]
    int a_row = (lq & 1) * 8 + lr;
    int a_k   = (lq >> 1) * 8;
    uint32_t a_off[4];
    #pragma unroll
    for (int mi = 0; mi < 4; mi++)
        a_off[mi] = uA + ((wm + mi * 16 + a_row) * BKP + a_k) * 2;
    // B x4 per n-pair: [n0-7,k0][n0-7,k8][n8-15,k0][n8-15,k8]
    int b_row = (lq >> 1) * 8 + lr;
    int b_k   = (lq & 1) * 8;
    uint32_t b_off[2];
    #pragma unroll
    for (int p = 0; p < 2; p++)
        b_off[p] = uB + ((wn + p * 16 + b_row) * BKP + b_k) * 2;

    float acc[4][4][4];
    #pragma unroll
    for (int mi = 0; mi < 4; mi++)
        #pragma unroll
        for (int ni = 0; ni < 4; ni++)
            #pragma unroll
            for (int r = 0; r < 4; r++) acc[mi][ni][r] = 0.f;

    int KT = K >> 5;

    // prologue: issue slabs 0 and 1
    #pragma unroll
    for (int s = 0; s < 2; s++) {
        cp16(sa + s * stgb,      Agp + s * 32);
        cp16(sa + s * stgb + 16, Agp + s * 32 + 8);
        cp16(sb + s * stgb,      Bgp + s * 32);
        cp16(sb + s * stgb + 16, Bgp + s * 32 + 8);
        asm volatile("cp.async.commit_group;\n");
    }

    int buf = 0;
    for (int kt = 0; kt < KT; kt++) {
        if (kt + 1 < KT) {
            asm volatile("cp.async.wait_group 1;\n");
        } else {
            asm volatile("cp.async.wait_group 0;\n");
        }
        __syncthreads();

        uint32_t stoff = buf * stgb;

        #pragma unroll
        for (int ks = 0; ks < 32; ks += 16) {
            unsigned af[4][4];
            unsigned bfr[2][4];
            #pragma unroll
            for (int mi = 0; mi < 4; mi++)
                LDMX4(af[mi][0], af[mi][1], af[mi][2], af[mi][3],
                      a_off[mi] + stoff + ks * 2);
            #pragma unroll
            for (int p = 0; p < 2; p++)
                LDMX4(bfr[p][0], bfr[p][1], bfr[p][2], bfr[p][3],
                      b_off[p] + stoff + ks * 2);
            #pragma unroll
            for (int mi = 0; mi < 4; mi++)
                #pragma unroll
                for (int ni = 0; ni < 4; ni++) {
                    int p = ni >> 1, hh = (ni & 1) * 2;
                    asm volatile(
                        "mma.sync.aligned.m16n8k16.row.col.f32.bf16.bf16.f32 "
                        "{%0,%1,%2,%3}, {%4,%5,%6,%7}, {%8,%9}, {%0,%1,%2,%3};\n"
                        : "+f"(acc[mi][ni][0]), "+f"(acc[mi][ni][1]),
                          "+f"(acc[mi][ni][2]), "+f"(acc[mi][ni][3])
                        : "r"(af[mi][0]), "r"(af[mi][1]),
                          "r"(af[mi][2]), "r"(af[mi][3]),
                          "r"(bfr[p][hh]), "r"(bfr[p][hh + 1]));
                }
        }

        if (kt + 2 < KT) {
            int s = (kt + 2) % STG;
            cp16(sa + s * stgb,      Agp + (kt + 2) * 32);
            cp16(sa + s * stgb + 16, Agp + (kt + 2) * 32 + 8);
            cp16(sb + s * stgb,      Bgp + (kt + 2) * 32);
            cp16(sb + s * stgb + 16, Bgp + (kt + 2) * 32 + 8);
            asm volatile("cp.async.commit_group;\n");
        }
        buf = (buf + 1) % STG;
    }

    // epilogue
    #pragma unroll
    for (int mi = 0; mi < 4; mi++) {
        #pragma unroll
        for (int ni = 0; ni < 4; ni++) {
            int col = bx * 128 + wn + ni * 8 + 2 * t;
            float2 bb = *(const float2*)&bias[col];
            #pragma unroll
            for (int h = 0; h < 2; h++) {
                int row = by * 128 + wm + mi * 16 + g + h * 8;
                float v0 = acc[mi][ni][2 * h + 0] + bb.x;
                float v1 = acc[mi][ni][2 * h + 1] + bb.y;
                if (EPI == 1) {
                    v0 = v0 / (1.f + __expf(-v0));
                    v1 = v1 / (1.f + __expf(-v1));
                }
                if (EPI == 2) {
                    float2 rr = *(const float2*)&res[(size_t)row * N + col];
                    v0 += rr.x; v1 += rr.y;
                }
                if (OBF) {
                    *(__nv_bfloat162*)((bf16_t*)Cout + (size_t)row * N + col) =
                        __floats2bfloat162_rn(v0, v1);
                } else {
                    *(float2*)((float*)Cout + (size_t)row * N + col) =
                        make_float2(v0, v1);
                }
            }
        }
    }
}

// ---------------------------------------------------------------------------
// Launch
// ---------------------------------------------------------------------------
#define HS_BYTES (2 * STG * 128 * BKP * 2)

extern "C" void kernel_launch(void* const* d_in, const int* in_sizes, int n_in,
                              void* d_out, int out_size)
{
    const float *x, *att_bias, *Wq, *bq, *Wk, *bk, *Wv, *bv, *Wo, *bo;
    const float *ln1g, *ln1b, *ln2g, *ln2b, *W1, *b1, *W2, *b2;
    const int *row, *col;

    if (in_sizes[1] == E_ * H_) {
        x        = (const float*)d_in[0];
        att_bias = (const float*)d_in[1];
        Wq = (const float*)d_in[2];  bq = (const float*)d_in[3];
        Wk = (const float*)d_in[4];  bk = (const float*)d_in[5];
        Wv = (const float*)d_in[6];  bv = (const float*)d_in[7];
        Wo = (const float*)d_in[8];  bo = (const float*)d_in[9];
        ln1g = (const float*)d_in[10]; ln1b = (const float*)d_in[11];
        ln2g = (const float*)d_in[12]; ln2b = (const float*)d_in[13];
        W1 = (const float*)d_in[14]; b1 = (const float*)d_in[15];
        W2 = (const float*)d_in[16]; b2 = (const float*)d_in[17];
        row = (const int*)d_in[18];  col = (const int*)d_in[19];
    } else {
        x   = (const float*)d_in[0];
        row = (const int*)d_in[1];
        col = (const int*)d_in[2];
        att_bias = (const float*)d_in[3];
        Wq = (const float*)d_in[4];  bq = (const float*)d_in[5];
        Wk = (const float*)d_in[6];  bk = (const float*)d_in[7];
        Wv = (const float*)d_in[8];  bv = (const float*)d_in[9];
        Wo = (const float*)d_in[10]; bo = (const float*)d_in[11];
        ln1g = (const float*)d_in[12]; ln1b = (const float*)d_in[13];
        ln2g = (const float*)d_in[14]; ln2b = (const float*)d_in[15];
        W1 = (const float*)d_in[16]; b1 = (const float*)d_in[17];
        W2 = (const float*)d_in[18]; b2 = (const float*)d_in[19];
    }

    bf16_t *pz, *pkb, *pvb, *pa, *ph, *pwq, *pwk, *pwv, *pwo, *pw1, *pw2;
    float *pq;
    int* pseg;
    cudaGetSymbolAddress((void**)&pz,  g_zb);
    cudaGetSymbolAddress((void**)&pq,  g_q);
    cudaGetSymbolAddress((void**)&pkb, g_kb);
    cudaGetSymbolAddress((void**)&pvb, g_vb);
    cudaGetSymbolAddress((void**)&pa,  g_attb);
    cudaGetSymbolAddress((void**)&ph,  g_hb);
    cudaGetSymbolAddress((void**)&pwq, g_wq);
    cudaGetSymbolAddress((void**)&pwk, g_wk);
    cudaGetSymbolAddress((void**)&pwv, g_wv);
    cudaGetSymbolAddress((void**)&pwo, g_wo);
    cudaGetSymbolAddress((void**)&pw1, g_w1);
    cudaGetSymbolAddress((void**)&pw2, g_w2);
    cudaGetSymbolAddress((void**)&pseg, g_seg);

    static bool attr_done = false;
    if (!attr_done) {
        cudaFuncSetAttribute(hgemm_kernel<0,0>, cudaFuncAttributeMaxDynamicSharedMemorySize, HS_BYTES);
        cudaFuncSetAttribute(hgemm_kernel<0,1>, cudaFuncAttributeMaxDynamicSharedMemorySize, HS_BYTES);
        cudaFuncSetAttribute(hgemm_kernel<2,0>, cudaFuncAttributeMaxDynamicSharedMemorySize, HS_BYTES);
        cudaFuncSetAttribute(hgemm_kernel<1,1>, cudaFuncAttributeMaxDynamicSharedMemorySize, HS_BYTES);
        attr_done = true;
    }

    float* out = (float*)d_out;

    dim3 t32(32, 8);
    // 0. weight transpose+cast to bf16
    wcast_kernel<<<dim3(C_ / 32, C_ / 32), t32>>>(Wq, pwq, C_, C_);
    wcast_kernel<<<dim3(C_ / 32, C_ / 32), t32>>>(Wk, pwk, C_, C_);
    wcast_kernel<<<dim3(C_ / 32, C_ / 32), t32>>>(Wv, pwv, C_, C_);
    wcast_kernel<<<dim3(C_ / 32, C_ / 32), t32>>>(Wo, pwo, C_, C_);
    wcast_kernel<<<dim3(HID_ / 32, C_ / 32), t32>>>(W1, pw1, C_, HID_);
    wcast_kernel<<<dim3(C_ / 32, HID_ / 32), t32>>>(W2, pw2, HID_, C_);

    // 1. z = LN1(x)  (bf16)
    ln_kernel<<<L_, 128>>>(x, ln1g, ln1b, pz);
    // 2. segment boundaries
    seg_kernel<<<E_ / 256, 256>>>(row, pseg);
    // 3. q (f32), k, v (bf16) projections
    dim3 gC(C_ / 128, L_ / 128);
    hgemm_kernel<0, 0><<<gC, 256, HS_BYTES>>>(pz, pwq, bq, nullptr, pq, L_, C_, C_);
    hgemm_kernel<0, 1><<<gC, 256, HS_BYTES>>>(pz, pwk, bk, nullptr, pkb, L_, C_, C_);
    hgemm_kernel<0, 1><<<gC, 256, HS_BYTES>>>(pz, pwv, bv, nullptr, pvb, L_, C_, C_);
    // 4. sparse attention (bf16 K/V gather, bf16 out)
    attn_kernel<<<L_, 256>>>(pq, pkb, pvb, att_bias, col, pseg, pa);
    // 5. out = x + att @ Wo + bo   (f32 out)
    hgemm_kernel<2, 0><<<gC, 256, HS_BYTES>>>(pa, pwo, bo, x, out, L_, C_, C_);
    // 6. z = LN2(out)  (bf16)
    ln_kernel<<<L_, 128>>>(out, ln2g, ln2b, pz);
    // 7. h = silu(z @ W1 + b1)  (bf16 out)
    dim3 gH(HID_ / 128, L_ / 128);
    hgemm_kernel<1, 1><<<gH, 256, HS_BYTES>>>(pz, pw1, b1, nullptr, ph, L_, HID_, C_);
    // 8. out = out + h @ W2 + b2  (f32 out, in-place residual)
    hgemm_kernel<2, 0><<<gC, 256, HS_BYTES>>>(ph, pw2, b2, out, out, L_, C_, HID_);
}